// round 10
// baseline (speedup 1.0000x reference)
#include <cuda_runtime.h>
#include <cuda_bf16.h>
#include <math.h>
#include <stdint.h>

#define BATCH 4
#define SEQ   4096
#define EMB   2048
#define HD    128
#define MTOT  (BATCH*SEQ)

// ---------------------------------------------------------------------------
// Device-global scratch (no allocation allowed)
// ---------------------------------------------------------------------------
static __device__ float g_cos[SEQ*(HD/2)];
static __device__ float g_sin[SEQ*(HD/2)];
static __device__ __nv_bfloat16 g_wthi[3*HD*EMB];   // [mat][n][k]
static __device__ __nv_bfloat16 g_wtlo[3*HD*EMB];
static __device__ __nv_bfloat16 g_Qhi[(size_t)MTOT*HD];   // [b*s][d]
static __device__ __nv_bfloat16 g_Qlo[(size_t)MTOT*HD];
static __device__ __nv_bfloat16 g_Khi[(size_t)MTOT*HD];
static __device__ __nv_bfloat16 g_Klo[(size_t)MTOT*HD];
static __device__ __nv_bfloat16 g_Vthi[(size_t)MTOT*HD];  // [b][d][s]
static __device__ __nv_bfloat16 g_Vtlo[(size_t)MTOT*HD];

// ---------------------------------------------------------------------------
// PTX helpers
// ---------------------------------------------------------------------------
__device__ __forceinline__ uint32_t smem_u32(const void* p) {
    uint32_t a;
    asm("{ .reg .u64 t; cvta.to.shared.u64 t, %1; cvt.u32.u64 %0, t; }" : "=r"(a) : "l"(p));
    return a;
}

#define SW128(off) ((off) ^ (((off) >> 3) & 0x70))

__device__ __forceinline__ void cpasync16(uint32_t dst, const void* src) {
    asm volatile("cp.async.cg.shared.global [%0], [%1], 16;" :: "r"(dst), "l"(src) : "memory");
}
#define CP_COMMIT()  asm volatile("cp.async.commit_group;" ::: "memory")
#define CP_WAIT2()   asm volatile("cp.async.wait_group 2;" ::: "memory")
#define CP_WAIT1()   asm volatile("cp.async.wait_group 1;" ::: "memory")
#define CP_WAIT0()   asm volatile("cp.async.wait_group 0;" ::: "memory")

#define BAR_SYNC(id, cnt)   asm volatile("bar.sync %0, %1;"   :: "r"(id), "r"(cnt) : "memory")
#define BAR_ARRIVE(id, cnt) asm volatile("bar.arrive %0, %1;" :: "r"(id), "r"(cnt) : "memory")
#define MEMBAR_CTA()        asm volatile("membar.cta;" ::: "memory")

#define STS128(addr, r0, r1, r2, r3) \
    asm volatile("st.shared.v4.b32 [%0], {%1,%2,%3,%4};" \
                 :: "r"(addr), "r"(r0), "r"(r1), "r"(r2), "r"(r3) : "memory")

__device__ __forceinline__ void ldsm4(uint32_t r[4], uint32_t addr) {
    asm volatile("ldmatrix.sync.aligned.m8n8.x4.shared.b16 {%0,%1,%2,%3}, [%4];"
                 : "=r"(r[0]), "=r"(r[1]), "=r"(r[2]), "=r"(r[3]) : "r"(addr));
}

__device__ __forceinline__ void mma16816(float c[4],
                                         const uint32_t a[4],
                                         uint32_t b0, uint32_t b1) {
    asm volatile(
        "mma.sync.aligned.m16n8k16.row.col.f32.bf16.bf16.f32 "
        "{%0,%1,%2,%3}, {%4,%5,%6,%7}, {%8,%9}, {%0,%1,%2,%3};"
        : "+f"(c[0]), "+f"(c[1]), "+f"(c[2]), "+f"(c[3])
        : "r"(a[0]), "r"(a[1]), "r"(a[2]), "r"(a[3]), "r"(b0), "r"(b1));
}

__device__ __forceinline__ void split_pack(float va, float vb,
                                           uint32_t& hi, uint32_t& lo) {
    __nv_bfloat16 ha = __float2bfloat16(va), hb = __float2bfloat16(vb);
    __nv_bfloat162 H(ha, hb);
    hi = *(uint32_t*)&H;
    __nv_bfloat162 L(__float2bfloat16(va - __bfloat162float(ha)),
                     __float2bfloat16(vb - __bfloat162float(hb)));
    lo = *(uint32_t*)&L;
}

// ---------------------------------------------------------------------------
// RoPE tables
// ---------------------------------------------------------------------------
__global__ void rope_table_kernel() {
    int idx = blockIdx.x * blockDim.x + threadIdx.x;
    if (idx >= SEQ * (HD/2)) return;
    int s = idx >> 6;
    int i = idx & 63;
    double freqd = exp(-(double)(2*i) * (9.210340371976184 / 128.0));
    float angle = (float)s * (float)freqd;
    float sn, cs;
    sincosf(angle, &sn, &cs);
    g_cos[idx] = cs;
    g_sin[idx] = sn;
}

// ---------------------------------------------------------------------------
// Weight splits (tiny)
// ---------------------------------------------------------------------------
__global__ void split_w_kernel(const float* __restrict__ Wq,
                               const float* __restrict__ Wk,
                               const float* __restrict__ Wv) {
    int idx = blockIdx.x * blockDim.x + threadIdx.x;   // 3*EMB*HD
    if (idx >= 3 * EMB * HD) return;
    int mat = idx / (EMB * HD);
    int r   = idx % (EMB * HD);
    int k = r / HD, n = r % HD;
    const float* W = (mat == 0) ? Wq : (mat == 1) ? Wk : Wv;
    float v = W[r];
    __nv_bfloat16 hi = __float2bfloat16(v);
    __nv_bfloat16 lo = __float2bfloat16(v - __bfloat162float(hi));
    g_wthi[(size_t)mat*HD*EMB + (size_t)n*EMB + k] = hi;
    g_wtlo[(size_t)mat*HD*EMB + (size_t)n*EMB + k] = lo;
}

// ---------------------------------------------------------------------------
// QKV projection: warp-specialized producer/consumer mma.sync (bf16 split).
// Producers fuse the x fp32 -> bf16 hi/lo split (LDG + cvt + STS); W via
// cp.async. Consumers unchanged (term-major MMA ordering).
// ---------------------------------------------------------------------------
#define KC       64
#define NCHUNK   (EMB / KC)          // 32
#define TILE_B   16384               // 128 rows x 128 bytes
#define STAGE_B  (4 * TILE_B)        // Ahi, Alo, Bhi, Blo
#define QKV_SMEM (1024 + 3 * STAGE_B)
#define NTHR     384

__global__ __launch_bounds__(NTHR, 1) void qkv_mma_kernel(
    const float* __restrict__ x,
    const float* __restrict__ Bq, const float* __restrict__ Bk,
    const float* __restrict__ Bv)
{
    extern __shared__ char smem_raw[];
    uint32_t base = (smem_u32(smem_raw) + 1023) & ~1023u;
    const int tid  = threadIdx.x;
    const int wid  = tid >> 5;
    const int lane = tid & 31;
    const int mat  = blockIdx.x;
    const int m0   = blockIdx.y * 128;

    const __nv_bfloat16* Bhi = g_wthi + (size_t)mat * HD * EMB;
    const __nv_bfloat16* Blo = g_wtlo + (size_t)mat * HD * EMB;
    const float* bias = (mat == 0) ? Bq : (mat == 1) ? Bk : Bv;

    if (wid >= 8) {
        // ------------- producer warps (8-11): x split + W cp.async -------------
        const int ptid = tid - 256;    // 0..127
        const float* Xb = x + (size_t)m0 * EMB;
        for (int i = 0; i < NCHUNK; i++) {
            const int s = i - (i / 3) * 3;
            if (i >= 3) BAR_SYNC(4 + s, NTHR);
            const int k0 = i * KC;
            const uint32_t st = base + s * STAGE_B;

            // W tiles via cp.async
            #pragma unroll
            for (int t = 0; t < 8; t++) {
                int idx = ptid + t * 128;
                int row = idx >> 3;
                int c16 = idx & 7;
                uint32_t off = SW128((uint32_t)(row * 128 + c16 * 16));
                const size_t g = (size_t)row * EMB + k0 + c16 * 8;
                cpasync16(st + 2*TILE_B + off, Bhi + g);
                cpasync16(st + 3*TILE_B + off, Blo + g);
            }
            CP_COMMIT();

            // A tile: LDG fp32 -> split -> STS (two halves, 4 groups each)
            #pragma unroll
            for (int half = 0; half < 2; half++) {
                float4 va[4], vb[4];
                #pragma unroll
                for (int g = 0; g < 4; g++) {
                    int idx = ptid + (half*4 + g) * 128;
                    int row = idx >> 3;
                    int c16 = idx & 7;
                    const float* src = Xb + (size_t)row * EMB + k0 + c16 * 8;
                    va[g] = *(const float4*)src;
                    vb[g] = *(const float4*)(src + 4);
                }
                #pragma unroll
                for (int g = 0; g < 4; g++) {
                    int idx = ptid + (half*4 + g) * 128;
                    int row = idx >> 3;
                    int c16 = idx & 7;
                    uint32_t h0,l0,h1,l1,h2,l2,h3,l3;
                    split_pack(va[g].x, va[g].y, h0, l0);
                    split_pack(va[g].z, va[g].w, h1, l1);
                    split_pack(vb[g].x, vb[g].y, h2, l2);
                    split_pack(vb[g].z, vb[g].w, h3, l3);
                    uint32_t off = SW128((uint32_t)(row * 128 + c16 * 16));
                    STS128(st + 0*TILE_B + off, h0, h1, h2, h3);
                    STS128(st + 1*TILE_B + off, l0, l1, l2, l3);
                }
            }

            if (i >= 2) {
                CP_WAIT2();
                MEMBAR_CTA();
                BAR_ARRIVE(1 + ((i - 2) % 3), NTHR);
            }
        }
        CP_WAIT1(); MEMBAR_CTA(); BAR_ARRIVE(1 + ((NCHUNK - 2) % 3), NTHR);
        CP_WAIT0(); MEMBAR_CTA(); BAR_ARRIVE(1 + ((NCHUNK - 1) % 3), NTHR);
        return;
    }

    // ---------------- consumer warps (0-7): all MMA ----------------
    const int wm = wid & 3;
    const int wn = wid >> 2;
    const int lr     = lane & 7;
    const int sel    = lane >> 3;
    const int rowadd = (sel & 1) * 8;
    const int kselb  = (sel >> 1) * 16;

    float acc[2][8][4];
    #pragma unroll
    for (int i = 0; i < 2; i++)
        #pragma unroll
        for (int j = 0; j < 8; j++)
            #pragma unroll
            for (int c = 0; c < 4; c++) acc[i][j][c] = 0.f;

    for (int i = 0; i < NCHUNK; i++) {
        const int s = i - (i / 3) * 3;
        BAR_SYNC(1 + s, NTHR);

        const uint32_t st   = base + s * STAGE_B;
        const uint32_t aHiB = st;
        const uint32_t aLoB = st + TILE_B;
        const uint32_t bHiB = st + 2*TILE_B;
        const uint32_t bLoB = st + 3*TILE_B;

        #pragma unroll
        for (int kk = 0; kk < 4; kk++) {
            const int kb = kk * 32;

            uint32_t ahi[2][4], alo[2][4];
            #pragma unroll
            for (int f = 0; f < 2; f++) {
                int row = wm*32 + f*16 + rowadd + lr;
                uint32_t byte = (uint32_t)(kb + kselb) ^ (uint32_t)((row & 7) * 16);
                uint32_t off  = (uint32_t)row * 128 + byte;
                ldsm4(ahi[f], aHiB + off);
                ldsm4(alo[f], aLoB + off);
            }
            uint32_t bhi[8][2], blo[8][2];
            #pragma unroll
            for (int jj = 0; jj < 4; jj++) {
                int row = wn*64 + jj*16 + rowadd + lr;
                uint32_t byte = (uint32_t)(kb + kselb) ^ (uint32_t)((row & 7) * 16);
                uint32_t off  = (uint32_t)row * 128 + byte;
                uint32_t t[4];
                ldsm4(t, bHiB + off);
                bhi[2*jj][0]   = t[0]; bhi[2*jj][1]   = t[2];
                bhi[2*jj+1][0] = t[1]; bhi[2*jj+1][1] = t[3];
                ldsm4(t, bLoB + off);
                blo[2*jj][0]   = t[0]; blo[2*jj][1]   = t[2];
                blo[2*jj+1][0] = t[1]; blo[2*jj+1][1] = t[3];
            }
            // Term-major: per-acc order (hh, hl, lh) preserved.
            #pragma unroll
            for (int f = 0; f < 2; f++)
                #pragma unroll
                for (int j = 0; j < 8; j++)
                    mma16816(acc[f][j], ahi[f], bhi[j][0], bhi[j][1]);
            #pragma unroll
            for (int f = 0; f < 2; f++)
                #pragma unroll
                for (int j = 0; j < 8; j++)
                    mma16816(acc[f][j], ahi[f], blo[j][0], blo[j][1]);
            #pragma unroll
            for (int f = 0; f < 2; f++)
                #pragma unroll
                for (int j = 0; j < 8; j++)
                    mma16816(acc[f][j], alo[f], bhi[j][0], bhi[j][1]);
        }

        BAR_ARRIVE(4 + s, NTHR);
    }

    // Epilogue: bias (+RoPE for Q,K), write bf16 hi/lo splits.
    const bool rope = (mat < 2);
    #pragma unroll
    for (int f = 0; f < 2; f++) {
        #pragma unroll
        for (int j = 0; j < 8; j++) {
            int c = wn*64 + j*8 + (lane & 3)*2;
            float b0v = bias[c], b1v = bias[c + 1];
            #pragma unroll
            for (int h = 0; h < 2; h++) {
                int row  = m0 + wm*32 + f*16 + (lane >> 2) + h*8;
                int spos = row & (SEQ - 1);
                float a = acc[f][j][2*h]     + b0v;
                float b = acc[f][j][2*h + 1] + b1v;
                if (rope) {
                    float cs = g_cos[spos*64 + (c >> 1)];
                    float sn = g_sin[spos*64 + (c >> 1)];
                    float ra = a*cs - b*sn;
                    float rb = b*cs + a*sn;
                    a = ra; b = rb;
                }
                uint32_t hi, lo;
                split_pack(a, b, hi, lo);
                if (mat == 0) {
                    *(uint32_t*)&g_Qhi[(size_t)row*HD + c] = hi;
                    *(uint32_t*)&g_Qlo[(size_t)row*HD + c] = lo;
                } else if (mat == 1) {
                    *(uint32_t*)&g_Khi[(size_t)row*HD + c] = hi;
                    *(uint32_t*)&g_Klo[(size_t)row*HD + c] = lo;
                } else {
                    size_t vb = ((size_t)(row >> 12) * HD) * SEQ + (row & (SEQ-1));
                    __nv_bfloat162 H = *(__nv_bfloat162*)&hi;
                    __nv_bfloat162 L = *(__nv_bfloat162*)&lo;
                    g_Vthi[vb + (size_t)c*SEQ]     = H.x;
                    g_Vthi[vb + (size_t)(c+1)*SEQ] = H.y;
                    g_Vtlo[vb + (size_t)c*SEQ]     = L.x;
                    g_Vtlo[vb + (size_t)(c+1)*SEQ] = L.y;
                }
            }
        }
    }
}

// ---------------------------------------------------------------------------
// Flash attention on mma.sync (unchanged from R9 passing kernel).
// ---------------------------------------------------------------------------
#define ATTN_SMEM (96*1024 + 1024)

__global__ __launch_bounds__(128, 2) void attn_mma_kernel(float* __restrict__ out)
{
    extern __shared__ char sm_raw[];
    const uint32_t base = (smem_u32(sm_raw) + 1023) & ~1023u;
    const uint32_t QHI = base,          QLO = base + 16384;
    const uint32_t KHI = base + 32768,  KLO = base + 49152;
    const uint32_t VTHI = base + 65536, VTLO = base + 81920;

    const int tid  = threadIdx.x;
    const int wid  = tid >> 5;
    const int lane = tid & 31;
    const int lr     = lane & 7;
    const int sel    = lane >> 3;
    const int rowadd = (sel & 1) * 8;
    const int kselb  = (sel >> 1) * 16;

    int bxx = blockIdx.x, t;
    if (bxx < 108)      t = 40 + bxx;
    else if (bxx < 148) t = bxx - 108;
    else                t = 403 - bxx;
    const int qt = 63 - (t >> 2);
    const int b  = t & 3;
    const int m0 = qt * 64;

    const __nv_bfloat16* qhi = g_Qhi + ((size_t)b*SEQ + m0) * HD;
    const __nv_bfloat16* qlo = g_Qlo + ((size_t)b*SEQ + m0) * HD;
    const __nv_bfloat16* khi = g_Khi + (size_t)b*SEQ*HD;
    const __nv_bfloat16* klo = g_Klo + (size_t)b*SEQ*HD;
    const __nv_bfloat16* vthi = g_Vthi + (size_t)b*HD*SEQ;
    const __nv_bfloat16* vtlo = g_Vtlo + (size_t)b*HD*SEQ;

    #pragma unroll
    for (int it = 0; it < 8; it++) {
        int i = tid + it * 128;
        int row = i >> 4, c = i & 15;
        uint32_t off = (uint32_t)((c >> 3) * 8192)
                     + SW128((uint32_t)(row * 128 + (c & 7) * 16));
        cpasync16(QHI + off, qhi + (size_t)row * HD + c * 8);
        cpasync16(QLO + off, qlo + (size_t)row * HD + c * 8);
    }
    CP_COMMIT();

    float o[16][4];
    #pragma unroll
    for (int nf = 0; nf < 16; nf++)
        #pragma unroll
        for (int c = 0; c < 4; c++) o[nf][c] = 0.f;
    float mrow0 = -INFINITY, mrow1 = -INFINITY;
    float lsum0 = 0.f, lsum1 = 0.f;
    const float scale = 0.08838834764831845f;

    for (int nt = 0; nt <= qt; nt++) {
        const int nb = nt * 64;
        if (nt) __syncthreads();

        #pragma unroll
        for (int it = 0; it < 8; it++) {
            int i = tid + it * 128;
            int row = i >> 4, c = i & 15;
            uint32_t off = (uint32_t)((c >> 3) * 8192)
                         + SW128((uint32_t)(row * 128 + (c & 7) * 16));
            const size_t g = (size_t)(nb + row) * HD + c * 8;
            cpasync16(KHI + off, khi + g);
            cpasync16(KLO + off, klo + g);
        }
        #pragma unroll
        for (int it = 0; it < 8; it++) {
            int i = tid + it * 128;
            int d = i >> 3, c = i & 7;
            uint32_t off = SW128((uint32_t)(d * 128 + c * 16));
            const size_t g = (size_t)d * SEQ + nb + c * 8;
            cpasync16(VTHI + off, vthi + g);
            cpasync16(VTLO + off, vtlo + g);
        }
        CP_COMMIT();
        CP_WAIT0();
        __syncthreads();

        float s[8][4];
        #pragma unroll
        for (int j = 0; j < 8; j++)
            #pragma unroll
            for (int c = 0; c < 4; c++) s[j][c] = 0.f;

        #pragma unroll
        for (int kd = 0; kd < 8; kd++) {
            const uint32_t blk = (uint32_t)((kd >> 2) * 8192);
            const uint32_t kb  = (uint32_t)((kd & 3) * 32 + kselb);
            uint32_t ahi[4], alo[4];
            {
                int row = wid*16 + rowadd + lr;
                uint32_t addr = blk + (uint32_t)row*128 + (kb ^ (uint32_t)((row & 7)*16));
                ldsm4(ahi, QHI + addr);
                ldsm4(alo, QLO + addr);
            }
            #pragma unroll
            for (int jp = 0; jp < 2; jp++) {
                int rowA = (2*jp)*16 + rowadd + lr;
                int rowB = (2*jp+1)*16 + rowadd + lr;
                uint32_t adA = blk + (uint32_t)rowA*128 + (kb ^ (uint32_t)((rowA & 7)*16));
                uint32_t adB = blk + (uint32_t)rowB*128 + (kb ^ (uint32_t)((rowB & 7)*16));
                uint32_t thA[4], tlA[4], thB[4], tlB[4];
                ldsm4(thA, KHI + adA);
                ldsm4(tlA, KLO + adA);
                ldsm4(thB, KHI + adB);
                ldsm4(tlB, KLO + adB);
                mma16816(s[4*jp],   ahi, thA[0], thA[2]);
                mma16816(s[4*jp+1], ahi, thA[1], thA[3]);
                mma16816(s[4*jp+2], ahi, thB[0], thB[2]);
                mma16816(s[4*jp+3], ahi, thB[1], thB[3]);
                mma16816(s[4*jp],   ahi, tlA[0], tlA[2]);
                mma16816(s[4*jp+1], ahi, tlA[1], tlA[3]);
                mma16816(s[4*jp+2], ahi, tlB[0], tlB[2]);
                mma16816(s[4*jp+3], ahi, tlB[1], tlB[3]);
                mma16816(s[4*jp],   alo, thA[0], thA[2]);
                mma16816(s[4*jp+1], alo, thA[1], thA[3]);
                mma16816(s[4*jp+2], alo, thB[0], thB[2]);
                mma16816(s[4*jp+3], alo, thB[1], thB[3]);
            }
        }

        const bool diag = (nt == qt);
        #pragma unroll
        for (int j = 0; j < 8; j++)
            #pragma unroll
            for (int c = 0; c < 4; c++) {
                float v = s[j][c] * scale;
                if (diag) {
                    int col = j*8 + (lane & 3)*2 + (c & 1);
                    int row = wid*16 + (lane >> 2) + (c >> 1)*8;
                    if (col > row) v = -1e30f;
                }
                s[j][c] = v;
            }

        float mx0 = -INFINITY, mx1 = -INFINITY;
        #pragma unroll
        for (int j = 0; j < 8; j++) {
            mx0 = fmaxf(mx0, fmaxf(s[j][0], s[j][1]));
            mx1 = fmaxf(mx1, fmaxf(s[j][2], s[j][3]));
        }
        mx0 = fmaxf(mx0, __shfl_xor_sync(0xffffffffu, mx0, 1));
        mx0 = fmaxf(mx0, __shfl_xor_sync(0xffffffffu, mx0, 2));
        mx1 = fmaxf(mx1, __shfl_xor_sync(0xffffffffu, mx1, 1));
        mx1 = fmaxf(mx1, __shfl_xor_sync(0xffffffffu, mx1, 2));
        float mn0 = fmaxf(mrow0, mx0), mn1 = fmaxf(mrow1, mx1);
        float al0 = __expf(mrow0 - mn0), al1 = __expf(mrow1 - mn1);
        mrow0 = mn0; mrow1 = mn1;
        float sum0 = 0.f, sum1 = 0.f;
        #pragma unroll
        for (int j = 0; j < 8; j++) {
            s[j][0] = __expf(s[j][0] - mn0); sum0 += s[j][0];
            s[j][1] = __expf(s[j][1] - mn0); sum0 += s[j][1];
            s[j][2] = __expf(s[j][2] - mn1); sum1 += s[j][2];
            s[j][3] = __expf(s[j][3] - mn1); sum1 += s[j][3];
        }
        sum0 += __shfl_xor_sync(0xffffffffu, sum0, 1);
        sum0 += __shfl_xor_sync(0xffffffffu, sum0, 2);
        sum1 += __shfl_xor_sync(0xffffffffu, sum1, 1);
        sum1 += __shfl_xor_sync(0xffffffffu, sum1, 2);
        lsum0 = lsum0 * al0 + sum0;
        lsum1 = lsum1 * al1 + sum1;

        #pragma unroll
        for (int nf = 0; nf < 16; nf++) {
            o[nf][0] *= al0; o[nf][1] *= al0;
            o[nf][2] *= al1; o[nf][3] *= al1;
        }

        uint32_t phi[4][4], plo[4][4];
        #pragma unroll
        for (int kk = 0; kk < 4; kk++) {
            split_pack(s[2*kk][0],   s[2*kk][1],   phi[kk][0], plo[kk][0]);
            split_pack(s[2*kk][2],   s[2*kk][3],   phi[kk][1], plo[kk][1]);
            split_pack(s[2*kk+1][0], s[2*kk+1][1], phi[kk][2], plo[kk][2]);
            split_pack(s[2*kk+1][2], s[2*kk+1][3], phi[kk][3], plo[kk][3]);
        }

        #pragma unroll
        for (int kk = 0; kk < 4; kk++) {
            const uint32_t kb = (uint32_t)(kk*32 + kselb);
            #pragma unroll
            for (int jp = 0; jp < 4; jp++) {
                int rowA = (2*jp)*16 + rowadd + lr;
                int rowB = (2*jp+1)*16 + rowadd + lr;
                uint32_t adA = (uint32_t)rowA*128 + (kb ^ (uint32_t)((rowA & 7)*16));
                uint32_t adB = (uint32_t)rowB*128 + (kb ^ (uint32_t)((rowB & 7)*16));
                uint32_t thA[4], tlA[4], thB[4], tlB[4];
                ldsm4(thA, VTHI + adA);
                ldsm4(tlA, VTLO + adA);
                ldsm4(thB, VTHI + adB);
                ldsm4(tlB, VTLO + adB);
                mma16816(o[4*jp],   phi[kk], thA[0], thA[2]);
                mma16816(o[4*jp+1], phi[kk], thA[1], thA[3]);
                mma16816(o[4*jp+2], phi[kk], thB[0], thB[2]);
                mma16816(o[4*jp+3], phi[kk], thB[1], thB[3]);
                mma16816(o[4*jp],   phi[kk], tlA[0], tlA[2]);
                mma16816(o[4*jp+1], phi[kk], tlA[1], tlA[3]);
                mma16816(o[4*jp+2], phi[kk], tlB[0], tlB[2]);
                mma16816(o[4*jp+3], phi[kk], tlB[1], tlB[3]);
                mma16816(o[4*jp],   plo[kk], thA[0], thA[2]);
                mma16816(o[4*jp+1], plo[kk], thA[1], thA[3]);
                mma16816(o[4*jp+2], plo[kk], thB[0], thB[2]);
                mma16816(o[4*jp+3], plo[kk], thB[1], thB[3]);
            }
        }
    }

    const float inv0 = 1.0f / lsum0;
    const float inv1 = 1.0f / lsum1;
    const size_t r0 = ((size_t)b*SEQ + m0 + wid*16 + (lane >> 2)) * HD;
    #pragma unroll
    for (int nf = 0; nf < 16; nf++) {
        int c = nf*8 + (lane & 3)*2;
        *(float2*)&out[r0 + c]          = make_float2(o[nf][0]*inv0, o[nf][1]*inv0);
        *(float2*)&out[r0 + 8*HD + c]   = make_float2(o[nf][2]*inv1, o[nf][3]*inv1);
    }
}

// ---------------------------------------------------------------------------
extern "C" void kernel_launch(void* const* d_in, const int* in_sizes, int n_in,
                              void* d_out, int out_size)
{
    const float* x  = (const float*)d_in[0];
    const float* Wq = (const float*)d_in[1];
    const float* bq = (const float*)d_in[2];
    const float* Wk = (const float*)d_in[3];
    const float* bk = (const float*)d_in[4];
    const float* Wv = (const float*)d_in[5];
    const float* bv = (const float*)d_in[6];
    float* out = (float*)d_out;

    rope_table_kernel<<<(SEQ*(HD/2) + 255)/256, 256>>>();
    split_w_kernel<<<(3*EMB*HD + 255)/256, 256>>>(Wq, Wk, Wv);

    cudaFuncSetAttribute(qkv_mma_kernel,
                         cudaFuncAttributeMaxDynamicSharedMemorySize, QKV_SMEM);
    dim3 g1(3, MTOT / 128);
    qkv_mma_kernel<<<g1, NTHR, QKV_SMEM>>>(x, bq, bk, bv);

    cudaFuncSetAttribute(attn_mma_kernel,
                         cudaFuncAttributeMaxDynamicSharedMemorySize, ATTN_SMEM);
    attn_mma_kernel<<<256, 128, ATTN_SMEM>>>(out);
}

// round 12
// speedup vs baseline: 1.0705x; 1.0705x over previous
#include <cuda_runtime.h>
#include <cuda_bf16.h>
#include <math.h>
#include <stdint.h>

#define BATCH 4
#define SEQ   4096
#define EMB   2048
#define HD    128
#define MTOT  (BATCH*SEQ)

// ---------------------------------------------------------------------------
// Device-global scratch (no allocation allowed)
// ---------------------------------------------------------------------------
static __device__ float g_cos[SEQ*(HD/2)];
static __device__ float g_sin[SEQ*(HD/2)];
static __device__ __nv_bfloat16 g_xhi[(size_t)MTOT*EMB];
static __device__ __nv_bfloat16 g_xlo[(size_t)MTOT*EMB];
static __device__ __nv_bfloat16 g_wthi[3*HD*EMB];   // [mat][n][k]
static __device__ __nv_bfloat16 g_wtlo[3*HD*EMB];
static __device__ __nv_bfloat16 g_Qhi[(size_t)MTOT*HD];   // [b*s][d]
static __device__ __nv_bfloat16 g_Qlo[(size_t)MTOT*HD];
static __device__ __nv_bfloat16 g_Khi[(size_t)MTOT*HD];
static __device__ __nv_bfloat16 g_Klo[(size_t)MTOT*HD];
static __device__ __nv_bfloat16 g_Vthi[(size_t)MTOT*HD];  // [b][d][s]
static __device__ __nv_bfloat16 g_Vtlo[(size_t)MTOT*HD];

// ---------------------------------------------------------------------------
// PTX helpers
// ---------------------------------------------------------------------------
__device__ __forceinline__ uint32_t smem_u32(const void* p) {
    uint32_t a;
    asm("{ .reg .u64 t; cvta.to.shared.u64 t, %1; cvt.u32.u64 %0, t; }" : "=r"(a) : "l"(p));
    return a;
}

#define SW128(off) ((off) ^ (((off) >> 3) & 0x70))

__device__ __forceinline__ void cpasync16(uint32_t dst, const void* src) {
    asm volatile("cp.async.cg.shared.global [%0], [%1], 16;" :: "r"(dst), "l"(src) : "memory");
}
#define CP_COMMIT()  asm volatile("cp.async.commit_group;" ::: "memory")
#define CP_WAIT2()   asm volatile("cp.async.wait_group 2;" ::: "memory")
#define CP_WAIT1()   asm volatile("cp.async.wait_group 1;" ::: "memory")
#define CP_WAIT0()   asm volatile("cp.async.wait_group 0;" ::: "memory")

#define BAR_SYNC(id, cnt)   asm volatile("bar.sync %0, %1;"   :: "r"(id), "r"(cnt) : "memory")
#define BAR_ARRIVE(id, cnt) asm volatile("bar.arrive %0, %1;" :: "r"(id), "r"(cnt) : "memory")
#define MEMBAR_CTA()        asm volatile("membar.cta;" ::: "memory")

__device__ __forceinline__ void ldsm4(uint32_t r[4], uint32_t addr) {
    asm volatile("ldmatrix.sync.aligned.m8n8.x4.shared.b16 {%0,%1,%2,%3}, [%4];"
                 : "=r"(r[0]), "=r"(r[1]), "=r"(r[2]), "=r"(r[3]) : "r"(addr));
}

__device__ __forceinline__ void mma16816(float c[4],
                                         const uint32_t a[4],
                                         uint32_t b0, uint32_t b1) {
    asm volatile(
        "mma.sync.aligned.m16n8k16.row.col.f32.bf16.bf16.f32 "
        "{%0,%1,%2,%3}, {%4,%5,%6,%7}, {%8,%9}, {%0,%1,%2,%3};"
        : "+f"(c[0]), "+f"(c[1]), "+f"(c[2]), "+f"(c[3])
        : "r"(a[0]), "r"(a[1]), "r"(a[2]), "r"(a[3]), "r"(b0), "r"(b1));
}

__device__ __forceinline__ void split_pack(float va, float vb,
                                           uint32_t& hi, uint32_t& lo) {
    __nv_bfloat16 ha = __float2bfloat16(va), hb = __float2bfloat16(vb);
    __nv_bfloat162 H(ha, hb);
    hi = *(uint32_t*)&H;
    __nv_bfloat162 L(__float2bfloat16(va - __bfloat162float(ha)),
                     __float2bfloat16(vb - __bfloat162float(hb)));
    lo = *(uint32_t*)&L;
}

// ---------------------------------------------------------------------------
// RoPE tables
// ---------------------------------------------------------------------------
__global__ void rope_table_kernel() {
    int idx = blockIdx.x * blockDim.x + threadIdx.x;
    if (idx >= SEQ * (HD/2)) return;
    int s = idx >> 6;
    int i = idx & 63;
    double freqd = exp(-(double)(2*i) * (9.210340371976184 / 128.0));
    float angle = (float)s * (float)freqd;
    float sn, cs;
    sincosf(angle, &sn, &cs);
    g_cos[idx] = cs;
    g_sin[idx] = sn;
}

// ---------------------------------------------------------------------------
// bf16 2-term splits of inputs
// ---------------------------------------------------------------------------
__global__ void split_x_kernel(const float* __restrict__ x) {
    size_t idx = (size_t)blockIdx.x * blockDim.x + threadIdx.x;   // per float4
    if (idx >= (size_t)MTOT * EMB / 4) return;
    float4 v = ((const float4*)x)[idx];
    __nv_bfloat16 h0 = __float2bfloat16(v.x);
    __nv_bfloat16 h1 = __float2bfloat16(v.y);
    __nv_bfloat16 h2 = __float2bfloat16(v.z);
    __nv_bfloat16 h3 = __float2bfloat16(v.w);
    __nv_bfloat16 l0 = __float2bfloat16(v.x - __bfloat162float(h0));
    __nv_bfloat16 l1 = __float2bfloat16(v.y - __bfloat162float(h1));
    __nv_bfloat16 l2 = __float2bfloat16(v.z - __bfloat162float(h2));
    __nv_bfloat16 l3 = __float2bfloat16(v.w - __bfloat162float(h3));
    ((__nv_bfloat162*)g_xhi)[2*idx]   = __nv_bfloat162(h0, h1);
    ((__nv_bfloat162*)g_xhi)[2*idx+1] = __nv_bfloat162(h2, h3);
    ((__nv_bfloat162*)g_xlo)[2*idx]   = __nv_bfloat162(l0, l1);
    ((__nv_bfloat162*)g_xlo)[2*idx+1] = __nv_bfloat162(l2, l3);
}

__global__ void split_w_kernel(const float* __restrict__ Wq,
                               const float* __restrict__ Wk,
                               const float* __restrict__ Wv) {
    int idx = blockIdx.x * blockDim.x + threadIdx.x;   // 3*EMB*HD
    if (idx >= 3 * EMB * HD) return;
    int mat = idx / (EMB * HD);
    int r   = idx % (EMB * HD);
    int k = r / HD, n = r % HD;
    const float* W = (mat == 0) ? Wq : (mat == 1) ? Wk : Wv;
    float v = W[r];
    __nv_bfloat16 hi = __float2bfloat16(v);
    __nv_bfloat16 lo = __float2bfloat16(v - __bfloat162float(hi));
    g_wthi[(size_t)mat*HD*EMB + (size_t)n*EMB + k] = hi;
    g_wtlo[(size_t)mat*HD*EMB + (size_t)n*EMB + k] = lo;
}

// ---------------------------------------------------------------------------
// QKV projection (R9 passing version): warp-specialized producer/consumer
// mma.sync, bf16 split, term-major ordering.
// ---------------------------------------------------------------------------
#define KC       64
#define NCHUNK   (EMB / KC)          // 32
#define TILE_B   16384               // 128 rows x 128 bytes
#define STAGE_B  (4 * TILE_B)        // Ahi, Alo, Bhi, Blo
#define QKV_SMEM (1024 + 3 * STAGE_B)
#define NTHR     384

__global__ __launch_bounds__(NTHR, 1) void qkv_mma_kernel(
    const float* __restrict__ Bq, const float* __restrict__ Bk,
    const float* __restrict__ Bv)
{
    extern __shared__ char smem_raw[];
    uint32_t base = (smem_u32(smem_raw) + 1023) & ~1023u;
    const int tid  = threadIdx.x;
    const int wid  = tid >> 5;
    const int lane = tid & 31;
    const int mat  = blockIdx.x;
    const int m0   = blockIdx.y * 128;

    const __nv_bfloat16* Ahi = g_xhi + (size_t)m0 * EMB;
    const __nv_bfloat16* Alo = g_xlo + (size_t)m0 * EMB;
    const __nv_bfloat16* Bhi = g_wthi + (size_t)mat * HD * EMB;
    const __nv_bfloat16* Blo = g_wtlo + (size_t)mat * HD * EMB;
    const float* bias = (mat == 0) ? Bq : (mat == 1) ? Bk : Bv;

    if (wid >= 8) {
        const int ptid = tid - 256;    // 0..127
        for (int i = 0; i < NCHUNK; i++) {
            const int s = i - (i / 3) * 3;
            if (i >= 3) BAR_SYNC(4 + s, NTHR);
            const int k0 = i * KC;
            const uint32_t st = base + s * STAGE_B;
            #pragma unroll
            for (int t = 0; t < 8; t++) {
                int idx = ptid + t * 128;
                int row = idx >> 3;
                int c16 = idx & 7;
                uint32_t off = SW128((uint32_t)(row * 128 + c16 * 16));
                const size_t g = (size_t)row * EMB + k0 + c16 * 8;
                cpasync16(st + 0*TILE_B + off, Ahi + g);
                cpasync16(st + 1*TILE_B + off, Alo + g);
                cpasync16(st + 2*TILE_B + off, Bhi + g);
                cpasync16(st + 3*TILE_B + off, Blo + g);
            }
            CP_COMMIT();
            if (i >= 2) {
                CP_WAIT2();
                MEMBAR_CTA();
                BAR_ARRIVE(1 + ((i - 2) % 3), NTHR);
            }
        }
        CP_WAIT1(); MEMBAR_CTA(); BAR_ARRIVE(1 + ((NCHUNK - 2) % 3), NTHR);
        CP_WAIT0(); MEMBAR_CTA(); BAR_ARRIVE(1 + ((NCHUNK - 1) % 3), NTHR);
        return;
    }

    const int wm = wid & 3;
    const int wn = wid >> 2;
    const int lr     = lane & 7;
    const int sel    = lane >> 3;
    const int rowadd = (sel & 1) * 8;
    const int kselb  = (sel >> 1) * 16;

    float acc[2][8][4];
    #pragma unroll
    for (int i = 0; i < 2; i++)
        #pragma unroll
        for (int j = 0; j < 8; j++)
            #pragma unroll
            for (int c = 0; c < 4; c++) acc[i][j][c] = 0.f;

    for (int i = 0; i < NCHUNK; i++) {
        const int s = i - (i / 3) * 3;
        BAR_SYNC(1 + s, NTHR);

        const uint32_t st   = base + s * STAGE_B;
        const uint32_t aHiB = st;
        const uint32_t aLoB = st + TILE_B;
        const uint32_t bHiB = st + 2*TILE_B;
        const uint32_t bLoB = st + 3*TILE_B;

        #pragma unroll
        for (int kk = 0; kk < 4; kk++) {
            const int kb = kk * 32;

            uint32_t ahi[2][4], alo[2][4];
            #pragma unroll
            for (int f = 0; f < 2; f++) {
                int row = wm*32 + f*16 + rowadd + lr;
                uint32_t byte = (uint32_t)(kb + kselb) ^ (uint32_t)((row & 7) * 16);
                uint32_t off  = (uint32_t)row * 128 + byte;
                ldsm4(ahi[f], aHiB + off);
                ldsm4(alo[f], aLoB + off);
            }
            uint32_t bhi[8][2], blo[8][2];
            #pragma unroll
            for (int jj = 0; jj < 4; jj++) {
                int row = wn*64 + jj*16 + rowadd + lr;
                uint32_t byte = (uint32_t)(kb + kselb) ^ (uint32_t)((row & 7) * 16);
                uint32_t off  = (uint32_t)row * 128 + byte;
                uint32_t t[4];
                ldsm4(t, bHiB + off);
                bhi[2*jj][0]   = t[0]; bhi[2*jj][1]   = t[2];
                bhi[2*jj+1][0] = t[1]; bhi[2*jj+1][1] = t[3];
                ldsm4(t, bLoB + off);
                blo[2*jj][0]   = t[0]; blo[2*jj][1]   = t[2];
                blo[2*jj+1][0] = t[1]; blo[2*jj+1][1] = t[3];
            }
            #pragma unroll
            for (int f = 0; f < 2; f++)
                #pragma unroll
                for (int j = 0; j < 8; j++)
                    mma16816(acc[f][j], ahi[f], bhi[j][0], bhi[j][1]);
            #pragma unroll
            for (int f = 0; f < 2; f++)
                #pragma unroll
                for (int j = 0; j < 8; j++)
                    mma16816(acc[f][j], ahi[f], blo[j][0], blo[j][1]);
            #pragma unroll
            for (int f = 0; f < 2; f++)
                #pragma unroll
                for (int j = 0; j < 8; j++)
                    mma16816(acc[f][j], alo[f], bhi[j][0], bhi[j][1]);
        }

        BAR_ARRIVE(4 + s, NTHR);
    }

    const bool rope = (mat < 2);
    #pragma unroll
    for (int f = 0; f < 2; f++) {
        #pragma unroll
        for (int j = 0; j < 8; j++) {
            int c = wn*64 + j*8 + (lane & 3)*2;
            float b0v = bias[c], b1v = bias[c + 1];
            #pragma unroll
            for (int h = 0; h < 2; h++) {
                int row  = m0 + wm*32 + f*16 + (lane >> 2) + h*8;
                int spos = row & (SEQ - 1);
                float a = acc[f][j][2*h]     + b0v;
                float b = acc[f][j][2*h + 1] + b1v;
                if (rope) {
                    float cs = g_cos[spos*64 + (c >> 1)];
                    float sn = g_sin[spos*64 + (c >> 1)];
                    float ra = a*cs - b*sn;
                    float rb = b*cs + a*sn;
                    a = ra; b = rb;
                }
                uint32_t hi, lo;
                split_pack(a, b, hi, lo);
                if (mat == 0) {
                    *(uint32_t*)&g_Qhi[(size_t)row*HD + c] = hi;
                    *(uint32_t*)&g_Qlo[(size_t)row*HD + c] = lo;
                } else if (mat == 1) {
                    *(uint32_t*)&g_Khi[(size_t)row*HD + c] = hi;
                    *(uint32_t*)&g_Klo[(size_t)row*HD + c] = lo;
                } else {
                    size_t vb = ((size_t)(row >> 12) * HD) * SEQ + (row & (SEQ-1));
                    __nv_bfloat162 H = *(__nv_bfloat162*)&hi;
                    __nv_bfloat162 L = *(__nv_bfloat162*)&lo;
                    g_Vthi[vb + (size_t)c*SEQ]     = H.x;
                    g_Vthi[vb + (size_t)(c+1)*SEQ] = H.y;
                    g_Vtlo[vb + (size_t)c*SEQ]     = L.x;
                    g_Vtlo[vb + (size_t)(c+1)*SEQ] = L.y;
                }
            }
        }
    }
}

// ---------------------------------------------------------------------------
// Flash attention: BM=64, BN=32, double-buffered K/V (loads overlap compute).
// smem: Q 32KB + 2 stages x (K 16KB + Vt 16KB) = 96KB, 2 CTAs/SM.
// Vt: 64B d-rows, chunk swizzle c ^= (d>>1)&3 (conflict-free ldmatrix).
// ---------------------------------------------------------------------------
#define ATTN_SMEM (96*1024 + 1024)

__global__ __launch_bounds__(128, 2) void attn_mma_kernel(float* __restrict__ out)
{
    extern __shared__ char sm_raw[];
    const uint32_t base = (smem_u32(sm_raw) + 1023) & ~1023u;
    const uint32_t QHI = base, QLO = base + 16384;
    const uint32_t STG = base + 32768;   // stage stride 32768: KHI, KLO(+8192), VHI(+16384), VLO(+24576)

    const int tid  = threadIdx.x;
    const int wid  = tid >> 5;
    const int lane = tid & 31;
    const int lr     = lane & 7;
    const int sel    = lane >> 3;
    const int rowadd = (sel & 1) * 8;
    const int kselb  = (sel >> 1) * 16;

    // Balanced causal task map
    int bxx = blockIdx.x, t;
    if (bxx < 108)      t = 40 + bxx;
    else if (bxx < 148) t = bxx - 108;
    else                t = 403 - bxx;
    const int qt = 63 - (t >> 2);
    const int b  = t & 3;
    const int m0 = qt * 64;

    const __nv_bfloat16* qhi = g_Qhi + ((size_t)b*SEQ + m0) * HD;
    const __nv_bfloat16* qlo = g_Qlo + ((size_t)b*SEQ + m0) * HD;
    const __nv_bfloat16* khi = g_Khi + (size_t)b*SEQ*HD;
    const __nv_bfloat16* klo = g_Klo + (size_t)b*SEQ*HD;
    const __nv_bfloat16* vthi = g_Vthi + (size_t)b*HD*SEQ;
    const __nv_bfloat16* vtlo = g_Vtlo + (size_t)b*HD*SEQ;

    // Q tile (group 0): 64 rows x 128 d, two 64-d blocks of 128B rows
    #pragma unroll
    for (int it = 0; it < 8; it++) {
        int i = tid + it * 128;
        int row = i >> 4, c = i & 15;
        uint32_t off = (uint32_t)((c >> 3) * 8192)
                     + SW128((uint32_t)(row * 128 + (c & 7) * 16));
        cpasync16(QHI + off, qhi + (size_t)row * HD + c * 8);
        cpasync16(QLO + off, qlo + (size_t)row * HD + c * 8);
    }
    CP_COMMIT();

    // Stage loader: K 32 rows x 256B (two 4KB blocks), Vt 128 x 64B rows
    auto load_stage = [&](int nt, int buf) {
        const int nb = nt * 32;
        const uint32_t S = STG + (uint32_t)buf * 32768u;
        #pragma unroll
        for (int it = 0; it < 4; it++) {
            int i = tid + it * 128;
            int row = i >> 4, c = i & 15;
            uint32_t off = (uint32_t)((c >> 3) * 4096)
                         + SW128((uint32_t)(row * 128 + (c & 7) * 16));
            const size_t g = (size_t)(nb + row) * HD + c * 8;
            cpasync16(S + off,        khi + g);
            cpasync16(S + 8192 + off, klo + g);
        }
        #pragma unroll
        for (int it = 0; it < 4; it++) {
            int i = tid + it * 128;
            int d = i >> 2, c = i & 3;
            uint32_t off = (uint32_t)(d * 64 + ((c ^ ((d >> 1) & 3)) << 4));
            const size_t g = (size_t)d * SEQ + nb + c * 8;
            cpasync16(S + 16384 + off, vthi + g);
            cpasync16(S + 24576 + off, vtlo + g);
        }
    };

    load_stage(0, 0); CP_COMMIT();   // group 1

    float o[16][4];
    #pragma unroll
    for (int nf = 0; nf < 16; nf++)
        #pragma unroll
        for (int c = 0; c < 4; c++) o[nf][c] = 0.f;
    float mrow0 = -INFINITY, mrow1 = -INFINITY;
    float lsum0 = 0.f, lsum1 = 0.f;
    const float scale = 0.08838834764831845f;

    const int ntiles = 2*qt + 2;
    for (int nt = 0; nt < ntiles; nt++) {
        const int buf = nt & 1;
        __syncthreads();   // all warps done reading buf^1 (prev compute)
        if (nt + 1 < ntiles) {
            load_stage(nt + 1, buf ^ 1);
            CP_COMMIT();
            CP_WAIT1();    // current stage (and Q) resident; prefetch in flight
        } else {
            CP_WAIT0();
        }
        __syncthreads();

        const uint32_t KH = STG + (uint32_t)buf * 32768u;
        const uint32_t KL = KH + 8192;
        const uint32_t VH = KH + 16384;
        const uint32_t VL = KH + 24576;

        // ---- S = Q K^T (3-term split, interleaved over 4 accs) ----
        float s[4][4];
        #pragma unroll
        for (int j = 0; j < 4; j++)
            #pragma unroll
            for (int c = 0; c < 4; c++) s[j][c] = 0.f;

        #pragma unroll
        for (int kd = 0; kd < 8; kd++) {
            const uint32_t blkq = (uint32_t)((kd >> 2) * 8192);
            const uint32_t blkk = (uint32_t)((kd >> 2) * 4096);
            const uint32_t kb   = (uint32_t)((kd & 3) * 32 + kselb);
            uint32_t ahi[4], alo[4];
            {
                int row = wid*16 + rowadd + lr;
                uint32_t addr = blkq + (uint32_t)row*128 + (kb ^ (uint32_t)((row & 7)*16));
                ldsm4(ahi, QHI + addr);
                ldsm4(alo, QLO + addr);
            }
            int rowA = rowadd + lr;          // K rows 0-15
            int rowB = 16 + rowadd + lr;     // K rows 16-31
            uint32_t adA = blkk + (uint32_t)rowA*128 + (kb ^ (uint32_t)((rowA & 7)*16));
            uint32_t adB = blkk + (uint32_t)rowB*128 + (kb ^ (uint32_t)((rowB & 7)*16));
            uint32_t thA[4], tlA[4], thB[4], tlB[4];
            ldsm4(thA, KH + adA);
            ldsm4(tlA, KL + adA);
            ldsm4(thB, KH + adB);
            ldsm4(tlB, KL + adB);
            mma16816(s[0], ahi, thA[0], thA[2]);
            mma16816(s[1], ahi, thA[1], thA[3]);
            mma16816(s[2], ahi, thB[0], thB[2]);
            mma16816(s[3], ahi, thB[1], thB[3]);
            mma16816(s[0], ahi, tlA[0], tlA[2]);
            mma16816(s[1], ahi, tlA[1], tlA[3]);
            mma16816(s[2], ahi, tlB[0], tlB[2]);
            mma16816(s[3], ahi, tlB[1], tlB[3]);
            mma16816(s[0], alo, thA[0], thA[2]);
            mma16816(s[1], alo, thA[1], thA[3]);
            mma16816(s[2], alo, thB[0], thB[2]);
            mma16816(s[3], alo, thB[1], thB[3]);
        }

        // ---- scale + causal mask ----
        const int nb = nt * 32;
        const bool diag = (nb + 31 > m0);
        const int rel = nb - m0;
        #pragma unroll
        for (int j = 0; j < 4; j++)
            #pragma unroll
            for (int c = 0; c < 4; c++) {
                float v = s[j][c] * scale;
                if (diag) {
                    int col = rel + j*8 + (lane & 3)*2 + (c & 1);
                    int row = wid*16 + (lane >> 2) + (c >> 1)*8;
                    if (col > row) v = -1e30f;
                }
                s[j][c] = v;
            }

        // ---- online softmax ----
        float mx0 = -INFINITY, mx1 = -INFINITY;
        #pragma unroll
        for (int j = 0; j < 4; j++) {
            mx0 = fmaxf(mx0, fmaxf(s[j][0], s[j][1]));
            mx1 = fmaxf(mx1, fmaxf(s[j][2], s[j][3]));
        }
        mx0 = fmaxf(mx0, __shfl_xor_sync(0xffffffffu, mx0, 1));
        mx0 = fmaxf(mx0, __shfl_xor_sync(0xffffffffu, mx0, 2));
        mx1 = fmaxf(mx1, __shfl_xor_sync(0xffffffffu, mx1, 1));
        mx1 = fmaxf(mx1, __shfl_xor_sync(0xffffffffu, mx1, 2));
        float mn0 = fmaxf(mrow0, mx0), mn1 = fmaxf(mrow1, mx1);
        float al0 = __expf(mrow0 - mn0), al1 = __expf(mrow1 - mn1);
        mrow0 = mn0; mrow1 = mn1;
        float sum0 = 0.f, sum1 = 0.f;
        #pragma unroll
        for (int j = 0; j < 4; j++) {
            s[j][0] = __expf(s[j][0] - mn0); sum0 += s[j][0];
            s[j][1] = __expf(s[j][1] - mn0); sum0 += s[j][1];
            s[j][2] = __expf(s[j][2] - mn1); sum1 += s[j][2];
            s[j][3] = __expf(s[j][3] - mn1); sum1 += s[j][3];
        }
        sum0 += __shfl_xor_sync(0xffffffffu, sum0, 1);
        sum0 += __shfl_xor_sync(0xffffffffu, sum0, 2);
        sum1 += __shfl_xor_sync(0xffffffffu, sum1, 1);
        sum1 += __shfl_xor_sync(0xffffffffu, sum1, 2);
        lsum0 = lsum0 * al0 + sum0;
        lsum1 = lsum1 * al1 + sum1;

        #pragma unroll
        for (int nf = 0; nf < 16; nf++) {
            o[nf][0] *= al0; o[nf][1] *= al0;
            o[nf][2] *= al1; o[nf][3] *= al1;
        }

        // ---- P -> bf16 hi/lo A-frags (2 k-chunks of 16 keys) ----
        uint32_t phi[2][4], plo[2][4];
        #pragma unroll
        for (int kk = 0; kk < 2; kk++) {
            split_pack(s[2*kk][0],   s[2*kk][1],   phi[kk][0], plo[kk][0]);
            split_pack(s[2*kk][2],   s[2*kk][3],   phi[kk][1], plo[kk][1]);
            split_pack(s[2*kk+1][0], s[2*kk+1][1], phi[kk][2], plo[kk][2]);
            split_pack(s[2*kk+1][2], s[2*kk+1][3], phi[kk][3], plo[kk][3]);
        }

        // ---- O += P @ V (3-term split, interleaved over jj pairs) ----
        #pragma unroll
        for (int kk = 0; kk < 2; kk++) {
            const uint32_t cbase = (uint32_t)(kk*2 + (kselb >> 4));
            #pragma unroll
            for (int jp = 0; jp < 4; jp++) {
                int rowA = (2*jp)*16 + rowadd + lr;     // d-rows
                int rowB = (2*jp+1)*16 + rowadd + lr;
                uint32_t adA = (uint32_t)rowA*64 + ((cbase ^ (uint32_t)((rowA >> 1) & 3)) << 4);
                uint32_t adB = (uint32_t)rowB*64 + ((cbase ^ (uint32_t)((rowB >> 1) & 3)) << 4);
                uint32_t thA[4], tlA[4], thB[4], tlB[4];
                ldsm4(thA, VH + adA);
                ldsm4(tlA, VL + adA);
                ldsm4(thB, VH + adB);
                ldsm4(tlB, VL + adB);
                mma16816(o[4*jp],   phi[kk], thA[0], thA[2]);
                mma16816(o[4*jp+1], phi[kk], thA[1], thA[3]);
                mma16816(o[4*jp+2], phi[kk], thB[0], thB[2]);
                mma16816(o[4*jp+3], phi[kk], thB[1], thB[3]);
                mma16816(o[4*jp],   phi[kk], tlA[0], tlA[2]);
                mma16816(o[4*jp+1], phi[kk], tlA[1], tlA[3]);
                mma16816(o[4*jp+2], phi[kk], tlB[0], tlB[2]);
                mma16816(o[4*jp+3], phi[kk], tlB[1], tlB[3]);
                mma16816(o[4*jp],   plo[kk], thA[0], thA[2]);
                mma16816(o[4*jp+1], plo[kk], thA[1], thA[3]);
                mma16816(o[4*jp+2], plo[kk], thB[0], thB[2]);
                mma16816(o[4*jp+3], plo[kk], thB[1], thB[3]);
            }
        }
    }

    const float inv0 = 1.0f / lsum0;
    const float inv1 = 1.0f / lsum1;
    const size_t r0 = ((size_t)b*SEQ + m0 + wid*16 + (lane >> 2)) * HD;
    #pragma unroll
    for (int nf = 0; nf < 16; nf++) {
        int c = nf*8 + (lane & 3)*2;
        *(float2*)&out[r0 + c]          = make_float2(o[nf][0]*inv0, o[nf][1]*inv0);
        *(float2*)&out[r0 + 8*HD + c]   = make_float2(o[nf][2]*inv1, o[nf][3]*inv1);
    }
}

// ---------------------------------------------------------------------------
extern "C" void kernel_launch(void* const* d_in, const int* in_sizes, int n_in,
                              void* d_out, int out_size)
{
    const float* x  = (const float*)d_in[0];
    const float* Wq = (const float*)d_in[1];
    const float* bq = (const float*)d_in[2];
    const float* Wk = (const float*)d_in[3];
    const float* bk = (const float*)d_in[4];
    const float* Wv = (const float*)d_in[5];
    const float* bv = (const float*)d_in[6];
    float* out = (float*)d_out;

    rope_table_kernel<<<(SEQ*(HD/2) + 255)/256, 256>>>();
    split_x_kernel<<<(MTOT*(EMB/4) + 255)/256, 256>>>(x);
    split_w_kernel<<<(3*EMB*HD + 255)/256, 256>>>(Wq, Wk, Wv);

    cudaFuncSetAttribute(qkv_mma_kernel,
                         cudaFuncAttributeMaxDynamicSharedMemorySize, QKV_SMEM);
    dim3 g1(3, MTOT / 128);
    qkv_mma_kernel<<<g1, NTHR, QKV_SMEM>>>(bq, bk, bv);

    cudaFuncSetAttribute(attn_mma_kernel,
                         cudaFuncAttributeMaxDynamicSharedMemorySize, ATTN_SMEM);
    attn_mma_kernel<<<256, 128, ATTN_SMEM>>>(out);
}

// round 13
// speedup vs baseline: 1.1094x; 1.0364x over previous
#include <cuda_runtime.h>
#include <cuda_fp16.h>
#include <math.h>
#include <stdint.h>

#define BATCH 4
#define SEQ   4096
#define EMB   2048
#define HD    128
#define MTOT  (BATCH*SEQ)

// ---------------------------------------------------------------------------
// Device-global scratch (no allocation allowed) — fp16 splits
// ---------------------------------------------------------------------------
static __device__ float g_cos[SEQ*(HD/2)];
static __device__ float g_sin[SEQ*(HD/2)];
static __device__ __half g_xhi[(size_t)MTOT*EMB];
static __device__ __half g_xlo[(size_t)MTOT*EMB];
static __device__ __half g_wthi[3*HD*EMB];   // [mat][n][k]
static __device__ __half g_wtlo[3*HD*EMB];
static __device__ __half g_Qhi[(size_t)MTOT*HD];   // [b*s][d]
static __device__ __half g_Qlo[(size_t)MTOT*HD];
static __device__ __half g_Khi[(size_t)MTOT*HD];
static __device__ __half g_Klo[(size_t)MTOT*HD];
static __device__ __half g_Vthi[(size_t)MTOT*HD];  // [b][d][s]
static __device__ __half g_Vtlo[(size_t)MTOT*HD];

// ---------------------------------------------------------------------------
// PTX helpers
// ---------------------------------------------------------------------------
__device__ __forceinline__ uint32_t smem_u32(const void* p) {
    uint32_t a;
    asm("{ .reg .u64 t; cvta.to.shared.u64 t, %1; cvt.u32.u64 %0, t; }" : "=r"(a) : "l"(p));
    return a;
}

#define SW128(off) ((off) ^ (((off) >> 3) & 0x70))

__device__ __forceinline__ void cpasync16(uint32_t dst, const void* src) {
    asm volatile("cp.async.cg.shared.global [%0], [%1], 16;" :: "r"(dst), "l"(src) : "memory");
}
#define CP_COMMIT()  asm volatile("cp.async.commit_group;" ::: "memory")
#define CP_WAIT2()   asm volatile("cp.async.wait_group 2;" ::: "memory")
#define CP_WAIT1()   asm volatile("cp.async.wait_group 1;" ::: "memory")
#define CP_WAIT0()   asm volatile("cp.async.wait_group 0;" ::: "memory")

#define BAR_SYNC(id, cnt)   asm volatile("bar.sync %0, %1;"   :: "r"(id), "r"(cnt) : "memory")
#define BAR_ARRIVE(id, cnt) asm volatile("bar.arrive %0, %1;" :: "r"(id), "r"(cnt) : "memory")
#define MEMBAR_CTA()        asm volatile("membar.cta;" ::: "memory")

__device__ __forceinline__ void ldsm4(uint32_t r[4], uint32_t addr) {
    asm volatile("ldmatrix.sync.aligned.m8n8.x4.shared.b16 {%0,%1,%2,%3}, [%4];"
                 : "=r"(r[0]), "=r"(r[1]), "=r"(r[2]), "=r"(r[3]) : "r"(addr));
}

// f16 inputs, fp32 accumulator
__device__ __forceinline__ void mma16816(float c[4],
                                         const uint32_t a[4],
                                         uint32_t b0, uint32_t b1) {
    asm volatile(
        "mma.sync.aligned.m16n8k16.row.col.f32.f16.f16.f32 "
        "{%0,%1,%2,%3}, {%4,%5,%6,%7}, {%8,%9}, {%0,%1,%2,%3};"
        : "+f"(c[0]), "+f"(c[1]), "+f"(c[2]), "+f"(c[3])
        : "r"(a[0]), "r"(a[1]), "r"(a[2]), "r"(a[3]), "r"(b0), "r"(b1));
}

// f16 inputs, f16 accumulator (2-reg C: reg0 = cols{0,1}, reg1 = cols{2,3})
__device__ __forceinline__ void mma16816h(uint32_t c[2],
                                          const uint32_t a[4],
                                          uint32_t b0, uint32_t b1) {
    asm volatile(
        "mma.sync.aligned.m16n8k16.row.col.f16.f16.f16.f16 "
        "{%0,%1}, {%2,%3,%4,%5}, {%6,%7}, {%0,%1};"
        : "+r"(c[0]), "+r"(c[1])
        : "r"(a[0]), "r"(a[1]), "r"(a[2]), "r"(a[3]), "r"(b0), "r"(b1));
}

// fp16 2-term split of a float pair
__device__ __forceinline__ void split_pack(float va, float vb,
                                           uint32_t& hi, uint32_t& lo) {
    __half ha = __float2half(va), hb = __float2half(vb);
    __half2 H(ha, hb);
    hi = *(uint32_t*)&H;
    __half2 L(__float2half(va - __half2float(ha)),
              __float2half(vb - __half2float(hb)));
    lo = *(uint32_t*)&L;
}

// ---------------------------------------------------------------------------
// RoPE tables
// ---------------------------------------------------------------------------
__global__ void rope_table_kernel() {
    int idx = blockIdx.x * blockDim.x + threadIdx.x;
    if (idx >= SEQ * (HD/2)) return;
    int s = idx >> 6;
    int i = idx & 63;
    double freqd = exp(-(double)(2*i) * (9.210340371976184 / 128.0));
    float angle = (float)s * (float)freqd;
    float sn, cs;
    sincosf(angle, &sn, &cs);
    g_cos[idx] = cs;
    g_sin[idx] = sn;
}

// ---------------------------------------------------------------------------
// fp16 2-term splits of inputs
// ---------------------------------------------------------------------------
__global__ void split_x_kernel(const float* __restrict__ x) {
    size_t idx = (size_t)blockIdx.x * blockDim.x + threadIdx.x;   // per float4
    if (idx >= (size_t)MTOT * EMB / 4) return;
    float4 v = ((const float4*)x)[idx];
    uint32_t h0, l0, h1, l1;
    split_pack(v.x, v.y, h0, l0);
    split_pack(v.z, v.w, h1, l1);
    ((uint32_t*)g_xhi)[2*idx]   = h0;
    ((uint32_t*)g_xhi)[2*idx+1] = h1;
    ((uint32_t*)g_xlo)[2*idx]   = l0;
    ((uint32_t*)g_xlo)[2*idx+1] = l1;
}

__global__ void split_w_kernel(const float* __restrict__ Wq,
                               const float* __restrict__ Wk,
                               const float* __restrict__ Wv) {
    int idx = blockIdx.x * blockDim.x + threadIdx.x;   // 3*EMB*HD
    if (idx >= 3 * EMB * HD) return;
    int mat = idx / (EMB * HD);
    int r   = idx % (EMB * HD);
    int k = r / HD, n = r % HD;
    const float* W = (mat == 0) ? Wq : (mat == 1) ? Wk : Wv;
    float v = W[r];
    __half hi = __float2half(v);
    __half lo = __float2half(v - __half2float(hi));
    g_wthi[(size_t)mat*HD*EMB + (size_t)n*EMB + k] = hi;
    g_wtlo[(size_t)mat*HD*EMB + (size_t)n*EMB + k] = lo;
}

// ---------------------------------------------------------------------------
// QKV projection: warp-specialized producer/consumer mma.sync, fp16 splits.
// hh term -> fp32 accumulators; hl + lh correction terms -> f16 accumulators
// (f16-acc HMMA runs at full rate vs half-rate fp32-acc).
// ---------------------------------------------------------------------------
#define KC       64
#define NCHUNK   (EMB / KC)          // 32
#define TILE_B   16384               // 128 rows x 128 bytes
#define STAGE_B  (4 * TILE_B)        // Ahi, Alo, Bhi, Blo
#define QKV_SMEM (1024 + 3 * STAGE_B)
#define NTHR     384

__global__ __launch_bounds__(NTHR, 1) void qkv_mma_kernel(
    const float* __restrict__ Bq, const float* __restrict__ Bk,
    const float* __restrict__ Bv)
{
    extern __shared__ char smem_raw[];
    uint32_t base = (smem_u32(smem_raw) + 1023) & ~1023u;
    const int tid  = threadIdx.x;
    const int wid  = tid >> 5;
    const int lane = tid & 31;
    const int mat  = blockIdx.x;
    const int m0   = blockIdx.y * 128;

    const __half* Ahi = g_xhi + (size_t)m0 * EMB;
    const __half* Alo = g_xlo + (size_t)m0 * EMB;
    const __half* Bhi = g_wthi + (size_t)mat * HD * EMB;
    const __half* Blo = g_wtlo + (size_t)mat * HD * EMB;
    const float* bias = (mat == 0) ? Bq : (mat == 1) ? Bk : Bv;

    if (wid >= 8) {
        const int ptid = tid - 256;    // 0..127
        for (int i = 0; i < NCHUNK; i++) {
            const int s = i - (i / 3) * 3;
            if (i >= 3) BAR_SYNC(4 + s, NTHR);
            const int k0 = i * KC;
            const uint32_t st = base + s * STAGE_B;
            #pragma unroll
            for (int t = 0; t < 8; t++) {
                int idx = ptid + t * 128;
                int row = idx >> 3;
                int c16 = idx & 7;
                uint32_t off = SW128((uint32_t)(row * 128 + c16 * 16));
                const size_t g = (size_t)row * EMB + k0 + c16 * 8;
                cpasync16(st + 0*TILE_B + off, Ahi + g);
                cpasync16(st + 1*TILE_B + off, Alo + g);
                cpasync16(st + 2*TILE_B + off, Bhi + g);
                cpasync16(st + 3*TILE_B + off, Blo + g);
            }
            CP_COMMIT();
            if (i >= 2) {
                CP_WAIT2();
                MEMBAR_CTA();
                BAR_ARRIVE(1 + ((i - 2) % 3), NTHR);
            }
        }
        CP_WAIT1(); MEMBAR_CTA(); BAR_ARRIVE(1 + ((NCHUNK - 2) % 3), NTHR);
        CP_WAIT0(); MEMBAR_CTA(); BAR_ARRIVE(1 + ((NCHUNK - 1) % 3), NTHR);
        return;
    }

    const int wm = wid & 3;
    const int wn = wid >> 2;
    const int lr     = lane & 7;
    const int sel    = lane >> 3;
    const int rowadd = (sel & 1) * 8;
    const int kselb  = (sel >> 1) * 16;

    float acc[2][8][4];          // hh term, fp32 acc
    uint32_t corr[2][8][2];      // hl+lh terms, f16 acc
    #pragma unroll
    for (int i = 0; i < 2; i++)
        #pragma unroll
        for (int j = 0; j < 8; j++) {
            #pragma unroll
            for (int c = 0; c < 4; c++) acc[i][j][c] = 0.f;
            corr[i][j][0] = 0u; corr[i][j][1] = 0u;
        }

    for (int i = 0; i < NCHUNK; i++) {
        const int s = i - (i / 3) * 3;
        BAR_SYNC(1 + s, NTHR);

        const uint32_t st   = base + s * STAGE_B;
        const uint32_t aHiB = st;
        const uint32_t aLoB = st + TILE_B;
        const uint32_t bHiB = st + 2*TILE_B;
        const uint32_t bLoB = st + 3*TILE_B;

        #pragma unroll
        for (int kk = 0; kk < 4; kk++) {
            const int kb = kk * 32;

            uint32_t ahi[2][4], alo[2][4];
            #pragma unroll
            for (int f = 0; f < 2; f++) {
                int row = wm*32 + f*16 + rowadd + lr;
                uint32_t byte = (uint32_t)(kb + kselb) ^ (uint32_t)((row & 7) * 16);
                uint32_t off  = (uint32_t)row * 128 + byte;
                ldsm4(ahi[f], aHiB + off);
                ldsm4(alo[f], aLoB + off);
            }
            uint32_t bhi[8][2], blo[8][2];
            #pragma unroll
            for (int jj = 0; jj < 4; jj++) {
                int row = wn*64 + jj*16 + rowadd + lr;
                uint32_t byte = (uint32_t)(kb + kselb) ^ (uint32_t)((row & 7) * 16);
                uint32_t off  = (uint32_t)row * 128 + byte;
                uint32_t t[4];
                ldsm4(t, bHiB + off);
                bhi[2*jj][0]   = t[0]; bhi[2*jj][1]   = t[2];
                bhi[2*jj+1][0] = t[1]; bhi[2*jj+1][1] = t[3];
                ldsm4(t, bLoB + off);
                blo[2*jj][0]   = t[0]; blo[2*jj][1]   = t[2];
                blo[2*jj+1][0] = t[1]; blo[2*jj+1][1] = t[3];
            }
            // hh -> fp32 acc (term-major)
            #pragma unroll
            for (int f = 0; f < 2; f++)
                #pragma unroll
                for (int j = 0; j < 8; j++)
                    mma16816(acc[f][j], ahi[f], bhi[j][0], bhi[j][1]);
            // hl -> f16 acc
            #pragma unroll
            for (int f = 0; f < 2; f++)
                #pragma unroll
                for (int j = 0; j < 8; j++)
                    mma16816h(corr[f][j], ahi[f], blo[j][0], blo[j][1]);
            // lh -> f16 acc
            #pragma unroll
            for (int f = 0; f < 2; f++)
                #pragma unroll
                for (int j = 0; j < 8; j++)
                    mma16816h(corr[f][j], alo[f], bhi[j][0], bhi[j][1]);
        }

        BAR_ARRIVE(4 + s, NTHR);
    }

    // Epilogue: merge f16 corrections, bias (+RoPE for Q,K), fp16 hi/lo out.
    const bool rope = (mat < 2);
    #pragma unroll
    for (int f = 0; f < 2; f++) {
        #pragma unroll
        for (int j = 0; j < 8; j++) {
            __half2 c01 = *(__half2*)&corr[f][j][0];
            __half2 c23 = *(__half2*)&corr[f][j][1];
            float vv[4];
            vv[0] = acc[f][j][0] + __half2float(c01.x);
            vv[1] = acc[f][j][1] + __half2float(c01.y);
            vv[2] = acc[f][j][2] + __half2float(c23.x);
            vv[3] = acc[f][j][3] + __half2float(c23.y);

            int c = wn*64 + j*8 + (lane & 3)*2;
            float b0v = bias[c], b1v = bias[c + 1];
            #pragma unroll
            for (int h = 0; h < 2; h++) {
                int row  = m0 + wm*32 + f*16 + (lane >> 2) + h*8;
                int spos = row & (SEQ - 1);
                float a = vv[2*h]     + b0v;
                float b = vv[2*h + 1] + b1v;
                if (rope) {
                    float cs = g_cos[spos*64 + (c >> 1)];
                    float sn = g_sin[spos*64 + (c >> 1)];
                    float ra = a*cs - b*sn;
                    float rb = b*cs + a*sn;
                    a = ra; b = rb;
                }
                uint32_t hi, lo;
                split_pack(a, b, hi, lo);
                if (mat == 0) {
                    *(uint32_t*)&g_Qhi[(size_t)row*HD + c] = hi;
                    *(uint32_t*)&g_Qlo[(size_t)row*HD + c] = lo;
                } else if (mat == 1) {
                    *(uint32_t*)&g_Khi[(size_t)row*HD + c] = hi;
                    *(uint32_t*)&g_Klo[(size_t)row*HD + c] = lo;
                } else {
                    size_t vb = ((size_t)(row >> 12) * HD) * SEQ + (row & (SEQ-1));
                    __half2 H = *(__half2*)&hi;
                    __half2 L = *(__half2*)&lo;
                    g_Vthi[vb + (size_t)c*SEQ]     = H.x;
                    g_Vthi[vb + (size_t)(c+1)*SEQ] = H.y;
                    g_Vtlo[vb + (size_t)c*SEQ]     = L.x;
                    g_Vtlo[vb + (size_t)(c+1)*SEQ] = L.y;
                }
            }
        }
    }
}

// ---------------------------------------------------------------------------
// Flash attention: BM=64, BN=64, 4 warps, fp16 3-term split, fp32 acc
// (R9 structure; dtype swap only).
// ---------------------------------------------------------------------------
#define ATTN_SMEM (96*1024 + 1024)

__global__ __launch_bounds__(128, 2) void attn_mma_kernel(float* __restrict__ out)
{
    extern __shared__ char sm_raw[];
    const uint32_t base = (smem_u32(sm_raw) + 1023) & ~1023u;
    const uint32_t QHI = base,          QLO = base + 16384;
    const uint32_t KHI = base + 32768,  KLO = base + 49152;
    const uint32_t VTHI = base + 65536, VTLO = base + 81920;

    const int tid  = threadIdx.x;
    const int wid  = tid >> 5;
    const int lane = tid & 31;
    const int lr     = lane & 7;
    const int sel    = lane >> 3;
    const int rowadd = (sel & 1) * 8;
    const int kselb  = (sel >> 1) * 16;

    int bxx = blockIdx.x, t;
    if (bxx < 108)      t = 40 + bxx;
    else if (bxx < 148) t = bxx - 108;
    else                t = 403 - bxx;
    const int qt = 63 - (t >> 2);
    const int b  = t & 3;
    const int m0 = qt * 64;

    const __half* qhi = g_Qhi + ((size_t)b*SEQ + m0) * HD;
    const __half* qlo = g_Qlo + ((size_t)b*SEQ + m0) * HD;
    const __half* khi = g_Khi + (size_t)b*SEQ*HD;
    const __half* klo = g_Klo + (size_t)b*SEQ*HD;
    const __half* vthi = g_Vthi + (size_t)b*HD*SEQ;
    const __half* vtlo = g_Vtlo + (size_t)b*HD*SEQ;

    #pragma unroll
    for (int it = 0; it < 8; it++) {
        int i = tid + it * 128;
        int row = i >> 4, c = i & 15;
        uint32_t off = (uint32_t)((c >> 3) * 8192)
                     + SW128((uint32_t)(row * 128 + (c & 7) * 16));
        cpasync16(QHI + off, qhi + (size_t)row * HD + c * 8);
        cpasync16(QLO + off, qlo + (size_t)row * HD + c * 8);
    }
    CP_COMMIT();

    float o[16][4];
    #pragma unroll
    for (int nf = 0; nf < 16; nf++)
        #pragma unroll
        for (int c = 0; c < 4; c++) o[nf][c] = 0.f;
    float mrow0 = -INFINITY, mrow1 = -INFINITY;
    float lsum0 = 0.f, lsum1 = 0.f;
    const float scale = 0.08838834764831845f;

    for (int nt = 0; nt <= qt; nt++) {
        const int nb = nt * 64;
        if (nt) __syncthreads();

        #pragma unroll
        for (int it = 0; it < 8; it++) {
            int i = tid + it * 128;
            int row = i >> 4, c = i & 15;
            uint32_t off = (uint32_t)((c >> 3) * 8192)
                         + SW128((uint32_t)(row * 128 + (c & 7) * 16));
            const size_t g = (size_t)(nb + row) * HD + c * 8;
            cpasync16(KHI + off, khi + g);
            cpasync16(KLO + off, klo + g);
        }
        #pragma unroll
        for (int it = 0; it < 8; it++) {
            int i = tid + it * 128;
            int d = i >> 3, c = i & 7;
            uint32_t off = SW128((uint32_t)(d * 128 + c * 16));
            const size_t g = (size_t)d * SEQ + nb + c * 8;
            cpasync16(VTHI + off, vthi + g);
            cpasync16(VTLO + off, vtlo + g);
        }
        CP_COMMIT();
        CP_WAIT0();
        __syncthreads();

        float s[8][4];
        #pragma unroll
        for (int j = 0; j < 8; j++)
            #pragma unroll
            for (int c = 0; c < 4; c++) s[j][c] = 0.f;

        #pragma unroll
        for (int kd = 0; kd < 8; kd++) {
            const uint32_t blk = (uint32_t)((kd >> 2) * 8192);
            const uint32_t kb  = (uint32_t)((kd & 3) * 32 + kselb);
            uint32_t ahi[4], alo[4];
            {
                int row = wid*16 + rowadd + lr;
                uint32_t addr = blk + (uint32_t)row*128 + (kb ^ (uint32_t)((row & 7)*16));
                ldsm4(ahi, QHI + addr);
                ldsm4(alo, QLO + addr);
            }
            #pragma unroll
            for (int jp = 0; jp < 2; jp++) {
                int rowA = (2*jp)*16 + rowadd + lr;
                int rowB = (2*jp+1)*16 + rowadd + lr;
                uint32_t adA = blk + (uint32_t)rowA*128 + (kb ^ (uint32_t)((rowA & 7)*16));
                uint32_t adB = blk + (uint32_t)rowB*128 + (kb ^ (uint32_t)((rowB & 7)*16));
                uint32_t thA[4], tlA[4], thB[4], tlB[4];
                ldsm4(thA, KHI + adA);
                ldsm4(tlA, KLO + adA);
                ldsm4(thB, KHI + adB);
                ldsm4(tlB, KLO + adB);
                mma16816(s[4*jp],   ahi, thA[0], thA[2]);
                mma16816(s[4*jp+1], ahi, thA[1], thA[3]);
                mma16816(s[4*jp+2], ahi, thB[0], thB[2]);
                mma16816(s[4*jp+3], ahi, thB[1], thB[3]);
                mma16816(s[4*jp],   ahi, tlA[0], tlA[2]);
                mma16816(s[4*jp+1], ahi, tlA[1], tlA[3]);
                mma16816(s[4*jp+2], ahi, tlB[0], tlB[2]);
                mma16816(s[4*jp+3], ahi, tlB[1], tlB[3]);
                mma16816(s[4*jp],   alo, thA[0], thA[2]);
                mma16816(s[4*jp+1], alo, thA[1], thA[3]);
                mma16816(s[4*jp+2], alo, thB[0], thB[2]);
                mma16816(s[4*jp+3], alo, thB[1], thB[3]);
            }
        }

        const bool diag = (nt == qt);
        #pragma unroll
        for (int j = 0; j < 8; j++)
            #pragma unroll
            for (int c = 0; c < 4; c++) {
                float v = s[j][c] * scale;
                if (diag) {
                    int col = j*8 + (lane & 3)*2 + (c & 1);
                    int row = wid*16 + (lane >> 2) + (c >> 1)*8;
                    if (col > row) v = -1e30f;
                }
                s[j][c] = v;
            }

        float mx0 = -INFINITY, mx1 = -INFINITY;
        #pragma unroll
        for (int j = 0; j < 8; j++) {
            mx0 = fmaxf(mx0, fmaxf(s[j][0], s[j][1]));
            mx1 = fmaxf(mx1, fmaxf(s[j][2], s[j][3]));
        }
        mx0 = fmaxf(mx0, __shfl_xor_sync(0xffffffffu, mx0, 1));
        mx0 = fmaxf(mx0, __shfl_xor_sync(0xffffffffu, mx0, 2));
        mx1 = fmaxf(mx1, __shfl_xor_sync(0xffffffffu, mx1, 1));
        mx1 = fmaxf(mx1, __shfl_xor_sync(0xffffffffu, mx1, 2));
        float mn0 = fmaxf(mrow0, mx0), mn1 = fmaxf(mrow1, mx1);
        float al0 = __expf(mrow0 - mn0), al1 = __expf(mrow1 - mn1);
        mrow0 = mn0; mrow1 = mn1;
        float sum0 = 0.f, sum1 = 0.f;
        #pragma unroll
        for (int j = 0; j < 8; j++) {
            s[j][0] = __expf(s[j][0] - mn0); sum0 += s[j][0];
            s[j][1] = __expf(s[j][1] - mn0); sum0 += s[j][1];
            s[j][2] = __expf(s[j][2] - mn1); sum1 += s[j][2];
            s[j][3] = __expf(s[j][3] - mn1); sum1 += s[j][3];
        }
        sum0 += __shfl_xor_sync(0xffffffffu, sum0, 1);
        sum0 += __shfl_xor_sync(0xffffffffu, sum0, 2);
        sum1 += __shfl_xor_sync(0xffffffffu, sum1, 1);
        sum1 += __shfl_xor_sync(0xffffffffu, sum1, 2);
        lsum0 = lsum0 * al0 + sum0;
        lsum1 = lsum1 * al1 + sum1;

        #pragma unroll
        for (int nf = 0; nf < 16; nf++) {
            o[nf][0] *= al0; o[nf][1] *= al0;
            o[nf][2] *= al1; o[nf][3] *= al1;
        }

        uint32_t phi[4][4], plo[4][4];
        #pragma unroll
        for (int kk = 0; kk < 4; kk++) {
            split_pack(s[2*kk][0],   s[2*kk][1],   phi[kk][0], plo[kk][0]);
            split_pack(s[2*kk][2],   s[2*kk][3],   phi[kk][1], plo[kk][1]);
            split_pack(s[2*kk+1][0], s[2*kk+1][1], phi[kk][2], plo[kk][2]);
            split_pack(s[2*kk+1][2], s[2*kk+1][3], phi[kk][3], plo[kk][3]);
        }

        #pragma unroll
        for (int kk = 0; kk < 4; kk++) {
            const uint32_t kb = (uint32_t)(kk*32 + kselb);
            #pragma unroll
            for (int jp = 0; jp < 4; jp++) {
                int rowA = (2*jp)*16 + rowadd + lr;
                int rowB = (2*jp+1)*16 + rowadd + lr;
                uint32_t adA = (uint32_t)rowA*128 + (kb ^ (uint32_t)((rowA & 7)*16));
                uint32_t adB = (uint32_t)rowB*128 + (kb ^ (uint32_t)((rowB & 7)*16));
                uint32_t thA[4], tlA[4], thB[4], tlB[4];
                ldsm4(thA, VTHI + adA);
                ldsm4(tlA, VTLO + adA);
                ldsm4(thB, VTHI + adB);
                ldsm4(tlB, VTLO + adB);
                mma16816(o[4*jp],   phi[kk], thA[0], thA[2]);
                mma16816(o[4*jp+1], phi[kk], thA[1], thA[3]);
                mma16816(o[4*jp+2], phi[kk], thB[0], thB[2]);
                mma16816(o[4*jp+3], phi[kk], thB[1], thB[3]);
                mma16816(o[4*jp],   phi[kk], tlA[0], tlA[2]);
                mma16816(o[4*jp+1], phi[kk], tlA[1], tlA[3]);
                mma16816(o[4*jp+2], phi[kk], tlB[0], tlB[2]);
                mma16816(o[4*jp+3], phi[kk], tlB[1], tlB[3]);
                mma16816(o[4*jp],   plo[kk], thA[0], thA[2]);
                mma16816(o[4*jp+1], plo[kk], thA[1], thA[3]);
                mma16816(o[4*jp+2], plo[kk], thB[0], thB[2]);
                mma16816(o[4*jp+3], plo[kk], thB[1], thB[3]);
            }
        }
    }

    const float inv0 = 1.0f / lsum0;
    const float inv1 = 1.0f / lsum1;
    const size_t r0 = ((size_t)b*SEQ + m0 + wid*16 + (lane >> 2)) * HD;
    #pragma unroll
    for (int nf = 0; nf < 16; nf++) {
        int c = nf*8 + (lane & 3)*2;
        *(float2*)&out[r0 + c]          = make_float2(o[nf][0]*inv0, o[nf][1]*inv0);
        *(float2*)&out[r0 + 8*HD + c]   = make_float2(o[nf][2]*inv1, o[nf][3]*inv1);
    }
}

// ---------------------------------------------------------------------------
extern "C" void kernel_launch(void* const* d_in, const int* in_sizes, int n_in,
                              void* d_out, int out_size)
{
    const float* x  = (const float*)d_in[0];
    const float* Wq = (const float*)d_in[1];
    const float* bq = (const float*)d_in[2];
    const float* Wk = (const float*)d_in[3];
    const float* bk = (const float*)d_in[4];
    const float* Wv = (const float*)d_in[5];
    const float* bv = (const float*)d_in[6];
    float* out = (float*)d_out;

    rope_table_kernel<<<(SEQ*(HD/2) + 255)/256, 256>>>();
    split_x_kernel<<<(MTOT*(EMB/4) + 255)/256, 256>>>(x);
    split_w_kernel<<<(3*EMB*HD + 255)/256, 256>>>(Wq, Wk, Wv);

    cudaFuncSetAttribute(qkv_mma_kernel,
                         cudaFuncAttributeMaxDynamicSharedMemorySize, QKV_SMEM);
    dim3 g1(3, MTOT / 128);
    qkv_mma_kernel<<<g1, NTHR, QKV_SMEM>>>(bq, bk, bv);

    cudaFuncSetAttribute(attn_mma_kernel,
                         cudaFuncAttributeMaxDynamicSharedMemorySize, ATTN_SMEM);
    attn_mma_kernel<<<256, 128, ATTN_SMEM>>>(out);
}

// round 14
// speedup vs baseline: 1.2982x; 1.1701x over previous
#include <cuda_runtime.h>
#include <cuda_fp16.h>
#include <math.h>
#include <stdint.h>

#define BATCH 4
#define SEQ   4096
#define EMB   2048
#define HD    128
#define MTOT  (BATCH*SEQ)

// ---------------------------------------------------------------------------
// Device-global scratch (no allocation allowed)
// ---------------------------------------------------------------------------
static __device__ float g_cos[SEQ*(HD/2)];
static __device__ float g_sin[SEQ*(HD/2)];
static __device__ __half g_x16[(size_t)MTOT*EMB];   // fp16(x), unsplit
static __device__ __half g_wthi[3*HD*EMB];          // [mat][n][k]
static __device__ __half g_wtlo[3*HD*EMB];
static __device__ __half g_Qhi[(size_t)MTOT*HD];    // [b*s][d]
static __device__ __half g_Qlo[(size_t)MTOT*HD];
static __device__ __half g_Khi[(size_t)MTOT*HD];
static __device__ __half g_Klo[(size_t)MTOT*HD];
static __device__ __half g_Vthi[(size_t)MTOT*HD];   // [b][d][s]
static __device__ __half g_Vtlo[(size_t)MTOT*HD];

// ---------------------------------------------------------------------------
// PTX helpers
// ---------------------------------------------------------------------------
__device__ __forceinline__ uint32_t smem_u32(const void* p) {
    uint32_t a;
    asm("{ .reg .u64 t; cvta.to.shared.u64 t, %1; cvt.u32.u64 %0, t; }" : "=r"(a) : "l"(p));
    return a;
}

#define SW128(off) ((off) ^ (((off) >> 3) & 0x70))

__device__ __forceinline__ void cpasync16(uint32_t dst, const void* src) {
    asm volatile("cp.async.cg.shared.global [%0], [%1], 16;" :: "r"(dst), "l"(src) : "memory");
}
#define CP_COMMIT()  asm volatile("cp.async.commit_group;" ::: "memory")
#define CP_WAIT2()   asm volatile("cp.async.wait_group 2;" ::: "memory")
#define CP_WAIT1()   asm volatile("cp.async.wait_group 1;" ::: "memory")
#define CP_WAIT0()   asm volatile("cp.async.wait_group 0;" ::: "memory")

#define BAR_SYNC(id, cnt)   asm volatile("bar.sync %0, %1;"   :: "r"(id), "r"(cnt) : "memory")
#define BAR_ARRIVE(id, cnt) asm volatile("bar.arrive %0, %1;" :: "r"(id), "r"(cnt) : "memory")
#define MEMBAR_CTA()        asm volatile("membar.cta;" ::: "memory")

__device__ __forceinline__ void ldsm4(uint32_t r[4], uint32_t addr) {
    asm volatile("ldmatrix.sync.aligned.m8n8.x4.shared.b16 {%0,%1,%2,%3}, [%4];"
                 : "=r"(r[0]), "=r"(r[1]), "=r"(r[2]), "=r"(r[3]) : "r"(addr));
}

// f16 inputs, fp32 accumulator
__device__ __forceinline__ void mma16816(float c[4],
                                         const uint32_t a[4],
                                         uint32_t b0, uint32_t b1) {
    asm volatile(
        "mma.sync.aligned.m16n8k16.row.col.f32.f16.f16.f32 "
        "{%0,%1,%2,%3}, {%4,%5,%6,%7}, {%8,%9}, {%0,%1,%2,%3};"
        : "+f"(c[0]), "+f"(c[1]), "+f"(c[2]), "+f"(c[3])
        : "r"(a[0]), "r"(a[1]), "r"(a[2]), "r"(a[3]), "r"(b0), "r"(b1));
}

// f16 inputs, f16 accumulator
__device__ __forceinline__ void mma16816h(uint32_t c[2],
                                          const uint32_t a[4],
                                          uint32_t b0, uint32_t b1) {
    asm volatile(
        "mma.sync.aligned.m16n8k16.row.col.f16.f16.f16.f16 "
        "{%0,%1}, {%2,%3,%4,%5}, {%6,%7}, {%0,%1};"
        : "+r"(c[0]), "+r"(c[1])
        : "r"(a[0]), "r"(a[1]), "r"(a[2]), "r"(a[3]), "r"(b0), "r"(b1));
}

__device__ __forceinline__ void split_pack(float va, float vb,
                                           uint32_t& hi, uint32_t& lo) {
    __half ha = __float2half(va), hb = __float2half(vb);
    __half2 H(ha, hb);
    hi = *(uint32_t*)&H;
    __half2 L(__float2half(va - __half2float(ha)),
              __float2half(vb - __half2float(hb)));
    lo = *(uint32_t*)&L;
}

// ---------------------------------------------------------------------------
// RoPE tables
// ---------------------------------------------------------------------------
__global__ void rope_table_kernel() {
    int idx = blockIdx.x * blockDim.x + threadIdx.x;
    if (idx >= SEQ * (HD/2)) return;
    int s = idx >> 6;
    int i = idx & 63;
    double freqd = exp(-(double)(2*i) * (9.210340371976184 / 128.0));
    float angle = (float)s * (float)freqd;
    float sn, cs;
    sincosf(angle, &sn, &cs);
    g_cos[idx] = cs;
    g_sin[idx] = sn;
}

// ---------------------------------------------------------------------------
// x -> fp16 (single conversion, no split)
// ---------------------------------------------------------------------------
__global__ void convert_x_kernel(const float* __restrict__ x) {
    size_t idx = (size_t)blockIdx.x * blockDim.x + threadIdx.x;   // per float4
    if (idx >= (size_t)MTOT * EMB / 4) return;
    float4 v = ((const float4*)x)[idx];
    __half2 a(__float2half(v.x), __float2half(v.y));
    __half2 b(__float2half(v.z), __float2half(v.w));
    ((uint32_t*)g_x16)[2*idx]   = *(uint32_t*)&a;
    ((uint32_t*)g_x16)[2*idx+1] = *(uint32_t*)&b;
}

__global__ void split_w_kernel(const float* __restrict__ Wq,
                               const float* __restrict__ Wk,
                               const float* __restrict__ Wv) {
    int idx = blockIdx.x * blockDim.x + threadIdx.x;   // 3*EMB*HD
    if (idx >= 3 * EMB * HD) return;
    int mat = idx / (EMB * HD);
    int r   = idx % (EMB * HD);
    int k = r / HD, n = r % HD;
    const float* W = (mat == 0) ? Wq : (mat == 1) ? Wk : Wv;
    float v = W[r];
    __half hi = __float2half(v);
    __half lo = __float2half(v - __half2float(hi));
    g_wthi[(size_t)mat*HD*EMB + (size_t)n*EMB + k] = hi;
    g_wtlo[(size_t)mat*HD*EMB + (size_t)n*EMB + k] = lo;
}

// ---------------------------------------------------------------------------
// QKV projection: 2-term (x16·w_hi fp32-acc + x16·w_lo f16-acc).
// Warp-specialized producer/consumer; stage = A + Whi + Wlo = 48KB.
// ---------------------------------------------------------------------------
#define KC       64
#define NCHUNK   (EMB / KC)          // 32
#define TILE_B   16384               // 128 rows x 128 bytes
#define STAGE_B  (3 * TILE_B)        // A, Bhi, Blo
#define QKV_SMEM (1024 + 3 * STAGE_B)
#define NTHR     384

__global__ __launch_bounds__(NTHR, 1) void qkv_mma_kernel(
    const float* __restrict__ Bq, const float* __restrict__ Bk,
    const float* __restrict__ Bv)
{
    extern __shared__ char smem_raw[];
    uint32_t base = (smem_u32(smem_raw) + 1023) & ~1023u;
    const int tid  = threadIdx.x;
    const int wid  = tid >> 5;
    const int lane = tid & 31;
    const int mat  = blockIdx.x;
    const int m0   = blockIdx.y * 128;

    const __half* A16 = g_x16 + (size_t)m0 * EMB;
    const __half* Bhi = g_wthi + (size_t)mat * HD * EMB;
    const __half* Blo = g_wtlo + (size_t)mat * HD * EMB;
    const float* bias = (mat == 0) ? Bq : (mat == 1) ? Bk : Bv;

    if (wid >= 8) {
        const int ptid = tid - 256;    // 0..127
        for (int i = 0; i < NCHUNK; i++) {
            const int s = i - (i / 3) * 3;
            if (i >= 3) BAR_SYNC(4 + s, NTHR);
            const int k0 = i * KC;
            const uint32_t st = base + s * STAGE_B;
            #pragma unroll
            for (int t = 0; t < 8; t++) {
                int idx = ptid + t * 128;
                int row = idx >> 3;
                int c16 = idx & 7;
                uint32_t off = SW128((uint32_t)(row * 128 + c16 * 16));
                const size_t g = (size_t)row * EMB + k0 + c16 * 8;
                cpasync16(st + 0*TILE_B + off, A16 + g);
                cpasync16(st + 1*TILE_B + off, Bhi + g);
                cpasync16(st + 2*TILE_B + off, Blo + g);
            }
            CP_COMMIT();
            if (i >= 2) {
                CP_WAIT2();
                MEMBAR_CTA();
                BAR_ARRIVE(1 + ((i - 2) % 3), NTHR);
            }
        }
        CP_WAIT1(); MEMBAR_CTA(); BAR_ARRIVE(1 + ((NCHUNK - 2) % 3), NTHR);
        CP_WAIT0(); MEMBAR_CTA(); BAR_ARRIVE(1 + ((NCHUNK - 1) % 3), NTHR);
        return;
    }

    const int wm = wid & 3;
    const int wn = wid >> 2;
    const int lr     = lane & 7;
    const int sel    = lane >> 3;
    const int rowadd = (sel & 1) * 8;
    const int kselb  = (sel >> 1) * 16;

    float acc[2][8][4];          // x·w_hi, fp32 acc
    uint32_t corr[2][8][2];      // x·w_lo, f16 acc
    #pragma unroll
    for (int i = 0; i < 2; i++)
        #pragma unroll
        for (int j = 0; j < 8; j++) {
            #pragma unroll
            for (int c = 0; c < 4; c++) acc[i][j][c] = 0.f;
            corr[i][j][0] = 0u; corr[i][j][1] = 0u;
        }

    for (int i = 0; i < NCHUNK; i++) {
        const int s = i - (i / 3) * 3;
        BAR_SYNC(1 + s, NTHR);

        const uint32_t st   = base + s * STAGE_B;
        const uint32_t aB   = st;
        const uint32_t bHiB = st + 1*TILE_B;
        const uint32_t bLoB = st + 2*TILE_B;

        #pragma unroll
        for (int kk = 0; kk < 4; kk++) {
            const int kb = kk * 32;

            uint32_t af[2][4];
            #pragma unroll
            for (int f = 0; f < 2; f++) {
                int row = wm*32 + f*16 + rowadd + lr;
                uint32_t byte = (uint32_t)(kb + kselb) ^ (uint32_t)((row & 7) * 16);
                uint32_t off  = (uint32_t)row * 128 + byte;
                ldsm4(af[f], aB + off);
            }
            uint32_t bhi[8][2], blo[8][2];
            #pragma unroll
            for (int jj = 0; jj < 4; jj++) {
                int row = wn*64 + jj*16 + rowadd + lr;
                uint32_t byte = (uint32_t)(kb + kselb) ^ (uint32_t)((row & 7) * 16);
                uint32_t off  = (uint32_t)row * 128 + byte;
                uint32_t t[4];
                ldsm4(t, bHiB + off);
                bhi[2*jj][0]   = t[0]; bhi[2*jj][1]   = t[2];
                bhi[2*jj+1][0] = t[1]; bhi[2*jj+1][1] = t[3];
                ldsm4(t, bLoB + off);
                blo[2*jj][0]   = t[0]; blo[2*jj][1]   = t[2];
                blo[2*jj+1][0] = t[1]; blo[2*jj+1][1] = t[3];
            }
            // main term (fp32 acc), term-major
            #pragma unroll
            for (int f = 0; f < 2; f++)
                #pragma unroll
                for (int j = 0; j < 8; j++)
                    mma16816(acc[f][j], af[f], bhi[j][0], bhi[j][1]);
            // correction term (f16 acc)
            #pragma unroll
            for (int f = 0; f < 2; f++)
                #pragma unroll
                for (int j = 0; j < 8; j++)
                    mma16816h(corr[f][j], af[f], blo[j][0], blo[j][1]);
        }

        BAR_ARRIVE(4 + s, NTHR);
    }

    // Epilogue: merge correction, bias (+RoPE for Q,K), fp16 hi/lo out.
    const bool rope = (mat < 2);
    #pragma unroll
    for (int f = 0; f < 2; f++) {
        #pragma unroll
        for (int j = 0; j < 8; j++) {
            __half2 c01 = *(__half2*)&corr[f][j][0];
            __half2 c23 = *(__half2*)&corr[f][j][1];
            float vv[4];
            vv[0] = acc[f][j][0] + __half2float(c01.x);
            vv[1] = acc[f][j][1] + __half2float(c01.y);
            vv[2] = acc[f][j][2] + __half2float(c23.x);
            vv[3] = acc[f][j][3] + __half2float(c23.y);

            int c = wn*64 + j*8 + (lane & 3)*2;
            float b0v = bias[c], b1v = bias[c + 1];
            #pragma unroll
            for (int h = 0; h < 2; h++) {
                int row  = m0 + wm*32 + f*16 + (lane >> 2) + h*8;
                int spos = row & (SEQ - 1);
                float a = vv[2*h]     + b0v;
                float b = vv[2*h + 1] + b1v;
                if (rope) {
                    float cs = g_cos[spos*64 + (c >> 1)];
                    float sn = g_sin[spos*64 + (c >> 1)];
                    float ra = a*cs - b*sn;
                    float rb = b*cs + a*sn;
                    a = ra; b = rb;
                }
                uint32_t hi, lo;
                split_pack(a, b, hi, lo);
                if (mat == 0) {
                    *(uint32_t*)&g_Qhi[(size_t)row*HD + c] = hi;
                    *(uint32_t*)&g_Qlo[(size_t)row*HD + c] = lo;
                } else if (mat == 1) {
                    *(uint32_t*)&g_Khi[(size_t)row*HD + c] = hi;
                    *(uint32_t*)&g_Klo[(size_t)row*HD + c] = lo;
                } else {
                    size_t vb = ((size_t)(row >> 12) * HD) * SEQ + (row & (SEQ-1));
                    __half2 H = *(__half2*)&hi;
                    __half2 L = *(__half2*)&lo;
                    g_Vthi[vb + (size_t)c*SEQ]     = H.x;
                    g_Vthi[vb + (size_t)(c+1)*SEQ] = H.y;
                    g_Vtlo[vb + (size_t)c*SEQ]     = L.x;
                    g_Vtlo[vb + (size_t)(c+1)*SEQ] = L.y;
                }
            }
        }
    }
}

// ---------------------------------------------------------------------------
// Flash attention: BM=64, BN=64, 4 warps, fp16 3-term split, fp32 acc
// (unchanged from R13 passing kernel).
// ---------------------------------------------------------------------------
#define ATTN_SMEM (96*1024 + 1024)

__global__ __launch_bounds__(128, 2) void attn_mma_kernel(float* __restrict__ out)
{
    extern __shared__ char sm_raw[];
    const uint32_t base = (smem_u32(sm_raw) + 1023) & ~1023u;
    const uint32_t QHI = base,          QLO = base + 16384;
    const uint32_t KHI = base + 32768,  KLO = base + 49152;
    const uint32_t VTHI = base + 65536, VTLO = base + 81920;

    const int tid  = threadIdx.x;
    const int wid  = tid >> 5;
    const int lane = tid & 31;
    const int lr     = lane & 7;
    const int sel    = lane >> 3;
    const int rowadd = (sel & 1) * 8;
    const int kselb  = (sel >> 1) * 16;

    int bxx = blockIdx.x, t;
    if (bxx < 108)      t = 40 + bxx;
    else if (bxx < 148) t = bxx - 108;
    else                t = 403 - bxx;
    const int qt = 63 - (t >> 2);
    const int b  = t & 3;
    const int m0 = qt * 64;

    const __half* qhi = g_Qhi + ((size_t)b*SEQ + m0) * HD;
    const __half* qlo = g_Qlo + ((size_t)b*SEQ + m0) * HD;
    const __half* khi = g_Khi + (size_t)b*SEQ*HD;
    const __half* klo = g_Klo + (size_t)b*SEQ*HD;
    const __half* vthi = g_Vthi + (size_t)b*HD*SEQ;
    const __half* vtlo = g_Vtlo + (size_t)b*HD*SEQ;

    #pragma unroll
    for (int it = 0; it < 8; it++) {
        int i = tid + it * 128;
        int row = i >> 4, c = i & 15;
        uint32_t off = (uint32_t)((c >> 3) * 8192)
                     + SW128((uint32_t)(row * 128 + (c & 7) * 16));
        cpasync16(QHI + off, qhi + (size_t)row * HD + c * 8);
        cpasync16(QLO + off, qlo + (size_t)row * HD + c * 8);
    }
    CP_COMMIT();

    float o[16][4];
    #pragma unroll
    for (int nf = 0; nf < 16; nf++)
        #pragma unroll
        for (int c = 0; c < 4; c++) o[nf][c] = 0.f;
    float mrow0 = -INFINITY, mrow1 = -INFINITY;
    float lsum0 = 0.f, lsum1 = 0.f;
    const float scale = 0.08838834764831845f;

    for (int nt = 0; nt <= qt; nt++) {
        const int nb = nt * 64;
        if (nt) __syncthreads();

        #pragma unroll
        for (int it = 0; it < 8; it++) {
            int i = tid + it * 128;
            int row = i >> 4, c = i & 15;
            uint32_t off = (uint32_t)((c >> 3) * 8192)
                         + SW128((uint32_t)(row * 128 + (c & 7) * 16));
            const size_t g = (size_t)(nb + row) * HD + c * 8;
            cpasync16(KHI + off, khi + g);
            cpasync16(KLO + off, klo + g);
        }
        #pragma unroll
        for (int it = 0; it < 8; it++) {
            int i = tid + it * 128;
            int d = i >> 3, c = i & 7;
            uint32_t off = SW128((uint32_t)(d * 128 + c * 16));
            const size_t g = (size_t)d * SEQ + nb + c * 8;
            cpasync16(VTHI + off, vthi + g);
            cpasync16(VTLO + off, vtlo + g);
        }
        CP_COMMIT();
        CP_WAIT0();
        __syncthreads();

        float s[8][4];
        #pragma unroll
        for (int j = 0; j < 8; j++)
            #pragma unroll
            for (int c = 0; c < 4; c++) s[j][c] = 0.f;

        #pragma unroll
        for (int kd = 0; kd < 8; kd++) {
            const uint32_t blk = (uint32_t)((kd >> 2) * 8192);
            const uint32_t kb  = (uint32_t)((kd & 3) * 32 + kselb);
            uint32_t ahi[4], alo[4];
            {
                int row = wid*16 + rowadd + lr;
                uint32_t addr = blk + (uint32_t)row*128 + (kb ^ (uint32_t)((row & 7)*16));
                ldsm4(ahi, QHI + addr);
                ldsm4(alo, QLO + addr);
            }
            #pragma unroll
            for (int jp = 0; jp < 2; jp++) {
                int rowA = (2*jp)*16 + rowadd + lr;
                int rowB = (2*jp+1)*16 + rowadd + lr;
                uint32_t adA = blk + (uint32_t)rowA*128 + (kb ^ (uint32_t)((rowA & 7)*16));
                uint32_t adB = blk + (uint32_t)rowB*128 + (kb ^ (uint32_t)((rowB & 7)*16));
                uint32_t thA[4], tlA[4], thB[4], tlB[4];
                ldsm4(thA, KHI + adA);
                ldsm4(tlA, KLO + adA);
                ldsm4(thB, KHI + adB);
                ldsm4(tlB, KLO + adB);
                mma16816(s[4*jp],   ahi, thA[0], thA[2]);
                mma16816(s[4*jp+1], ahi, thA[1], thA[3]);
                mma16816(s[4*jp+2], ahi, thB[0], thB[2]);
                mma16816(s[4*jp+3], ahi, thB[1], thB[3]);
                mma16816(s[4*jp],   ahi, tlA[0], tlA[2]);
                mma16816(s[4*jp+1], ahi, tlA[1], tlA[3]);
                mma16816(s[4*jp+2], ahi, tlB[0], tlB[2]);
                mma16816(s[4*jp+3], ahi, tlB[1], tlB[3]);
                mma16816(s[4*jp],   alo, thA[0], thA[2]);
                mma16816(s[4*jp+1], alo, thA[1], thA[3]);
                mma16816(s[4*jp+2], alo, thB[0], thB[2]);
                mma16816(s[4*jp+3], alo, thB[1], thB[3]);
            }
        }

        const bool diag = (nt == qt);
        #pragma unroll
        for (int j = 0; j < 8; j++)
            #pragma unroll
            for (int c = 0; c < 4; c++) {
                float v = s[j][c] * scale;
                if (diag) {
                    int col = j*8 + (lane & 3)*2 + (c & 1);
                    int row = wid*16 + (lane >> 2) + (c >> 1)*8;
                    if (col > row) v = -1e30f;
                }
                s[j][c] = v;
            }

        float mx0 = -INFINITY, mx1 = -INFINITY;
        #pragma unroll
        for (int j = 0; j < 8; j++) {
            mx0 = fmaxf(mx0, fmaxf(s[j][0], s[j][1]));
            mx1 = fmaxf(mx1, fmaxf(s[j][2], s[j][3]));
        }
        mx0 = fmaxf(mx0, __shfl_xor_sync(0xffffffffu, mx0, 1));
        mx0 = fmaxf(mx0, __shfl_xor_sync(0xffffffffu, mx0, 2));
        mx1 = fmaxf(mx1, __shfl_xor_sync(0xffffffffu, mx1, 1));
        mx1 = fmaxf(mx1, __shfl_xor_sync(0xffffffffu, mx1, 2));
        float mn0 = fmaxf(mrow0, mx0), mn1 = fmaxf(mrow1, mx1);
        float al0 = __expf(mrow0 - mn0), al1 = __expf(mrow1 - mn1);
        mrow0 = mn0; mrow1 = mn1;
        float sum0 = 0.f, sum1 = 0.f;
        #pragma unroll
        for (int j = 0; j < 8; j++) {
            s[j][0] = __expf(s[j][0] - mn0); sum0 += s[j][0];
            s[j][1] = __expf(s[j][1] - mn0); sum0 += s[j][1];
            s[j][2] = __expf(s[j][2] - mn1); sum1 += s[j][2];
            s[j][3] = __expf(s[j][3] - mn1); sum1 += s[j][3];
        }
        sum0 += __shfl_xor_sync(0xffffffffu, sum0, 1);
        sum0 += __shfl_xor_sync(0xffffffffu, sum0, 2);
        sum1 += __shfl_xor_sync(0xffffffffu, sum1, 1);
        sum1 += __shfl_xor_sync(0xffffffffu, sum1, 2);
        lsum0 = lsum0 * al0 + sum0;
        lsum1 = lsum1 * al1 + sum1;

        #pragma unroll
        for (int nf = 0; nf < 16; nf++) {
            o[nf][0] *= al0; o[nf][1] *= al0;
            o[nf][2] *= al1; o[nf][3] *= al1;
        }

        uint32_t phi[4][4], plo[4][4];
        #pragma unroll
        for (int kk = 0; kk < 4; kk++) {
            split_pack(s[2*kk][0],   s[2*kk][1],   phi[kk][0], plo[kk][0]);
            split_pack(s[2*kk][2],   s[2*kk][3],   phi[kk][1], plo[kk][1]);
            split_pack(s[2*kk+1][0], s[2*kk+1][1], phi[kk][2], plo[kk][2]);
            split_pack(s[2*kk+1][2], s[2*kk+1][3], phi[kk][3], plo[kk][3]);
        }

        #pragma unroll
        for (int kk = 0; kk < 4; kk++) {
            const uint32_t kb = (uint32_t)(kk*32 + kselb);
            #pragma unroll
            for (int jp = 0; jp < 4; jp++) {
                int rowA = (2*jp)*16 + rowadd + lr;
                int rowB = (2*jp+1)*16 + rowadd + lr;
                uint32_t adA = (uint32_t)rowA*128 + (kb ^ (uint32_t)((rowA & 7)*16));
                uint32_t adB = (uint32_t)rowB*128 + (kb ^ (uint32_t)((rowB & 7)*16));
                uint32_t thA[4], tlA[4], thB[4], tlB[4];
                ldsm4(thA, VTHI + adA);
                ldsm4(tlA, VTLO + adA);
                ldsm4(thB, VTHI + adB);
                ldsm4(tlB, VTLO + adB);
                mma16816(o[4*jp],   phi[kk], thA[0], thA[2]);
                mma16816(o[4*jp+1], phi[kk], thA[1], thA[3]);
                mma16816(o[4*jp+2], phi[kk], thB[0], thB[2]);
                mma16816(o[4*jp+3], phi[kk], thB[1], thB[3]);
                mma16816(o[4*jp],   phi[kk], tlA[0], tlA[2]);
                mma16816(o[4*jp+1], phi[kk], tlA[1], tlA[3]);
                mma16816(o[4*jp+2], phi[kk], tlB[0], tlB[2]);
                mma16816(o[4*jp+3], phi[kk], tlB[1], tlB[3]);
                mma16816(o[4*jp],   plo[kk], thA[0], thA[2]);
                mma16816(o[4*jp+1], plo[kk], thA[1], thA[3]);
                mma16816(o[4*jp+2], plo[kk], thB[0], thB[2]);
                mma16816(o[4*jp+3], plo[kk], thB[1], thB[3]);
            }
        }
    }

    const float inv0 = 1.0f / lsum0;
    const float inv1 = 1.0f / lsum1;
    const size_t r0 = ((size_t)b*SEQ + m0 + wid*16 + (lane >> 2)) * HD;
    #pragma unroll
    for (int nf = 0; nf < 16; nf++) {
        int c = nf*8 + (lane & 3)*2;
        *(float2*)&out[r0 + c]          = make_float2(o[nf][0]*inv0, o[nf][1]*inv0);
        *(float2*)&out[r0 + 8*HD + c]   = make_float2(o[nf][2]*inv1, o[nf][3]*inv1);
    }
}

// ---------------------------------------------------------------------------
extern "C" void kernel_launch(void* const* d_in, const int* in_sizes, int n_in,
                              void* d_out, int out_size)
{
    const float* x  = (const float*)d_in[0];
    const float* Wq = (const float*)d_in[1];
    const float* bq = (const float*)d_in[2];
    const float* Wk = (const float*)d_in[3];
    const float* bk = (const float*)d_in[4];
    const float* Wv = (const float*)d_in[5];
    const float* bv = (const float*)d_in[6];
    float* out = (float*)d_out;

    rope_table_kernel<<<(SEQ*(HD/2) + 255)/256, 256>>>();
    convert_x_kernel<<<(MTOT*(EMB/4) + 255)/256, 256>>>(x);
    split_w_kernel<<<(3*EMB*HD + 255)/256, 256>>>(Wq, Wk, Wv);

    cudaFuncSetAttribute(qkv_mma_kernel,
                         cudaFuncAttributeMaxDynamicSharedMemorySize, QKV_SMEM);
    dim3 g1(3, MTOT / 128);
    qkv_mma_kernel<<<g1, NTHR, QKV_SMEM>>>(bq, bk, bv);

    cudaFuncSetAttribute(attn_mma_kernel,
                         cudaFuncAttributeMaxDynamicSharedMemorySize, ATTN_SMEM);
    attn_mma_kernel<<<256, 128, ATTN_SMEM>>>(out);
}

// round 15
// speedup vs baseline: 1.4809x; 1.1408x over previous
#include <cuda_runtime.h>
#include <cuda_fp16.h>
#include <math.h>
#include <stdint.h>

#define BATCH 4
#define SEQ   4096
#define EMB   2048
#define HD    128
#define MTOT  (BATCH*SEQ)

// ---------------------------------------------------------------------------
// Device-global scratch (no allocation allowed)
// ---------------------------------------------------------------------------
static __device__ float g_cos[SEQ*(HD/2)];
static __device__ float g_sin[SEQ*(HD/2)];
static __device__ __half g_x16[(size_t)MTOT*EMB];   // fp16(x), unsplit
static __device__ __half g_wthi[3*HD*EMB];          // [mat][n][k]
static __device__ __half g_wtlo[3*HD*EMB];
static __device__ __half g_Q16[(size_t)MTOT*HD];    // fp16(Q), unsplit
static __device__ __half g_Khi[(size_t)MTOT*HD];
static __device__ __half g_Klo[(size_t)MTOT*HD];
static __device__ __half g_Vthi[(size_t)MTOT*HD];   // [b][d][s]
static __device__ __half g_Vtlo[(size_t)MTOT*HD];

// ---------------------------------------------------------------------------
// PTX helpers
// ---------------------------------------------------------------------------
__device__ __forceinline__ uint32_t smem_u32(const void* p) {
    uint32_t a;
    asm("{ .reg .u64 t; cvta.to.shared.u64 t, %1; cvt.u32.u64 %0, t; }" : "=r"(a) : "l"(p));
    return a;
}

#define SW128(off) ((off) ^ (((off) >> 3) & 0x70))

__device__ __forceinline__ void cpasync16(uint32_t dst, const void* src) {
    asm volatile("cp.async.cg.shared.global [%0], [%1], 16;" :: "r"(dst), "l"(src) : "memory");
}
#define CP_COMMIT()  asm volatile("cp.async.commit_group;" ::: "memory")
#define CP_WAIT2()   asm volatile("cp.async.wait_group 2;" ::: "memory")
#define CP_WAIT1()   asm volatile("cp.async.wait_group 1;" ::: "memory")
#define CP_WAIT0()   asm volatile("cp.async.wait_group 0;" ::: "memory")

#define BAR_SYNC(id, cnt)   asm volatile("bar.sync %0, %1;"   :: "r"(id), "r"(cnt) : "memory")
#define BAR_ARRIVE(id, cnt) asm volatile("bar.arrive %0, %1;" :: "r"(id), "r"(cnt) : "memory")
#define MEMBAR_CTA()        asm volatile("membar.cta;" ::: "memory")

__device__ __forceinline__ void ldsm4(uint32_t r[4], uint32_t addr) {
    asm volatile("ldmatrix.sync.aligned.m8n8.x4.shared.b16 {%0,%1,%2,%3}, [%4];"
                 : "=r"(r[0]), "=r"(r[1]), "=r"(r[2]), "=r"(r[3]) : "r"(addr));
}

// f16 inputs, fp32 accumulator
__device__ __forceinline__ void mma16816(float c[4],
                                         const uint32_t a[4],
                                         uint32_t b0, uint32_t b1) {
    asm volatile(
        "mma.sync.aligned.m16n8k16.row.col.f32.f16.f16.f32 "
        "{%0,%1,%2,%3}, {%4,%5,%6,%7}, {%8,%9}, {%0,%1,%2,%3};"
        : "+f"(c[0]), "+f"(c[1]), "+f"(c[2]), "+f"(c[3])
        : "r"(a[0]), "r"(a[1]), "r"(a[2]), "r"(a[3]), "r"(b0), "r"(b1));
}

// f16 inputs, f16 accumulator
__device__ __forceinline__ void mma16816h(uint32_t c[2],
                                          const uint32_t a[4],
                                          uint32_t b0, uint32_t b1) {
    asm volatile(
        "mma.sync.aligned.m16n8k16.row.col.f16.f16.f16.f16 "
        "{%0,%1}, {%2,%3,%4,%5}, {%6,%7}, {%0,%1};"
        : "+r"(c[0]), "+r"(c[1])
        : "r"(a[0]), "r"(a[1]), "r"(a[2]), "r"(a[3]), "r"(b0), "r"(b1));
}

__device__ __forceinline__ void split_pack(float va, float vb,
                                           uint32_t& hi, uint32_t& lo) {
    __half ha = __float2half(va), hb = __float2half(vb);
    __half2 H(ha, hb);
    hi = *(uint32_t*)&H;
    __half2 L(__float2half(va - __half2float(ha)),
              __float2half(vb - __half2float(hb)));
    lo = *(uint32_t*)&L;
}

__device__ __forceinline__ uint32_t pack16(float va, float vb) {
    __half2 H(__float2half(va), __float2half(vb));
    return *(uint32_t*)&H;
}

// ---------------------------------------------------------------------------
// RoPE tables
// ---------------------------------------------------------------------------
__global__ void rope_table_kernel() {
    int idx = blockIdx.x * blockDim.x + threadIdx.x;
    if (idx >= SEQ * (HD/2)) return;
    int s = idx >> 6;
    int i = idx & 63;
    double freqd = exp(-(double)(2*i) * (9.210340371976184 / 128.0));
    float angle = (float)s * (float)freqd;
    float sn, cs;
    sincosf(angle, &sn, &cs);
    g_cos[idx] = cs;
    g_sin[idx] = sn;
}

// ---------------------------------------------------------------------------
// x -> fp16 (single conversion)
// ---------------------------------------------------------------------------
__global__ void convert_x_kernel(const float* __restrict__ x) {
    size_t idx = (size_t)blockIdx.x * blockDim.x + threadIdx.x;   // per float4
    if (idx >= (size_t)MTOT * EMB / 4) return;
    float4 v = ((const float4*)x)[idx];
    ((uint32_t*)g_x16)[2*idx]   = pack16(v.x, v.y);
    ((uint32_t*)g_x16)[2*idx+1] = pack16(v.z, v.w);
}

__global__ void split_w_kernel(const float* __restrict__ Wq,
                               const float* __restrict__ Wk,
                               const float* __restrict__ Wv) {
    int idx = blockIdx.x * blockDim.x + threadIdx.x;   // 3*EMB*HD
    if (idx >= 3 * EMB * HD) return;
    int mat = idx / (EMB * HD);
    int r   = idx % (EMB * HD);
    int k = r / HD, n = r % HD;
    const float* W = (mat == 0) ? Wq : (mat == 1) ? Wk : Wv;
    float v = W[r];
    __half hi = __float2half(v);
    __half lo = __float2half(v - __half2float(hi));
    g_wthi[(size_t)mat*HD*EMB + (size_t)n*EMB + k] = hi;
    g_wtlo[(size_t)mat*HD*EMB + (size_t)n*EMB + k] = lo;
}

// ---------------------------------------------------------------------------
// QKV projection: 2-term (x16·w_hi fp32-acc + x16·w_lo f16-acc).
// Warp-specialized producer/consumer; stage = A + Whi + Wlo = 48KB.
// ---------------------------------------------------------------------------
#define KC       64
#define NCHUNK   (EMB / KC)          // 32
#define TILE_B   16384               // 128 rows x 128 bytes
#define STAGE_B  (3 * TILE_B)        // A, Bhi, Blo
#define QKV_SMEM (1024 + 3 * STAGE_B)
#define NTHR     384

__global__ __launch_bounds__(NTHR, 1) void qkv_mma_kernel(
    const float* __restrict__ Bq, const float* __restrict__ Bk,
    const float* __restrict__ Bv)
{
    extern __shared__ char smem_raw[];
    uint32_t base = (smem_u32(smem_raw) + 1023) & ~1023u;
    const int tid  = threadIdx.x;
    const int wid  = tid >> 5;
    const int lane = tid & 31;
    const int mat  = blockIdx.x;
    const int m0   = blockIdx.y * 128;

    const __half* A16 = g_x16 + (size_t)m0 * EMB;
    const __half* Bhi = g_wthi + (size_t)mat * HD * EMB;
    const __half* Blo = g_wtlo + (size_t)mat * HD * EMB;
    const float* bias = (mat == 0) ? Bq : (mat == 1) ? Bk : Bv;

    if (wid >= 8) {
        const int ptid = tid - 256;    // 0..127
        for (int i = 0; i < NCHUNK; i++) {
            const int s = i - (i / 3) * 3;
            if (i >= 3) BAR_SYNC(4 + s, NTHR);
            const int k0 = i * KC;
            const uint32_t st = base + s * STAGE_B;
            #pragma unroll
            for (int t = 0; t < 8; t++) {
                int idx = ptid + t * 128;
                int row = idx >> 3;
                int c16 = idx & 7;
                uint32_t off = SW128((uint32_t)(row * 128 + c16 * 16));
                const size_t g = (size_t)row * EMB + k0 + c16 * 8;
                cpasync16(st + 0*TILE_B + off, A16 + g);
                cpasync16(st + 1*TILE_B + off, Bhi + g);
                cpasync16(st + 2*TILE_B + off, Blo + g);
            }
            CP_COMMIT();
            if (i >= 2) {
                CP_WAIT2();
                MEMBAR_CTA();
                BAR_ARRIVE(1 + ((i - 2) % 3), NTHR);
            }
        }
        CP_WAIT1(); MEMBAR_CTA(); BAR_ARRIVE(1 + ((NCHUNK - 2) % 3), NTHR);
        CP_WAIT0(); MEMBAR_CTA(); BAR_ARRIVE(1 + ((NCHUNK - 1) % 3), NTHR);
        return;
    }

    const int wm = wid & 3;
    const int wn = wid >> 2;
    const int lr     = lane & 7;
    const int sel    = lane >> 3;
    const int rowadd = (sel & 1) * 8;
    const int kselb  = (sel >> 1) * 16;

    float acc[2][8][4];          // x·w_hi, fp32 acc
    uint32_t corr[2][8][2];      // x·w_lo, f16 acc
    #pragma unroll
    for (int i = 0; i < 2; i++)
        #pragma unroll
        for (int j = 0; j < 8; j++) {
            #pragma unroll
            for (int c = 0; c < 4; c++) acc[i][j][c] = 0.f;
            corr[i][j][0] = 0u; corr[i][j][1] = 0u;
        }

    for (int i = 0; i < NCHUNK; i++) {
        const int s = i - (i / 3) * 3;
        BAR_SYNC(1 + s, NTHR);

        const uint32_t st   = base + s * STAGE_B;
        const uint32_t aB   = st;
        const uint32_t bHiB = st + 1*TILE_B;
        const uint32_t bLoB = st + 2*TILE_B;

        #pragma unroll
        for (int kk = 0; kk < 4; kk++) {
            const int kb = kk * 32;

            uint32_t af[2][4];
            #pragma unroll
            for (int f = 0; f < 2; f++) {
                int row = wm*32 + f*16 + rowadd + lr;
                uint32_t byte = (uint32_t)(kb + kselb) ^ (uint32_t)((row & 7) * 16);
                uint32_t off  = (uint32_t)row * 128 + byte;
                ldsm4(af[f], aB + off);
            }
            uint32_t bhi[8][2], blo[8][2];
            #pragma unroll
            for (int jj = 0; jj < 4; jj++) {
                int row = wn*64 + jj*16 + rowadd + lr;
                uint32_t byte = (uint32_t)(kb + kselb) ^ (uint32_t)((row & 7) * 16);
                uint32_t off  = (uint32_t)row * 128 + byte;
                uint32_t t[4];
                ldsm4(t, bHiB + off);
                bhi[2*jj][0]   = t[0]; bhi[2*jj][1]   = t[2];
                bhi[2*jj+1][0] = t[1]; bhi[2*jj+1][1] = t[3];
                ldsm4(t, bLoB + off);
                blo[2*jj][0]   = t[0]; blo[2*jj][1]   = t[2];
                blo[2*jj+1][0] = t[1]; blo[2*jj+1][1] = t[3];
            }
            #pragma unroll
            for (int f = 0; f < 2; f++)
                #pragma unroll
                for (int j = 0; j < 8; j++)
                    mma16816(acc[f][j], af[f], bhi[j][0], bhi[j][1]);
            #pragma unroll
            for (int f = 0; f < 2; f++)
                #pragma unroll
                for (int j = 0; j < 8; j++)
                    mma16816h(corr[f][j], af[f], blo[j][0], blo[j][1]);
        }

        BAR_ARRIVE(4 + s, NTHR);
    }

    // Epilogue: merge correction, bias (+RoPE for Q,K); Q unsplit fp16,
    // K split hi/lo, V transposed split hi/lo.
    const bool rope = (mat < 2);
    #pragma unroll
    for (int f = 0; f < 2; f++) {
        #pragma unroll
        for (int j = 0; j < 8; j++) {
            __half2 c01 = *(__half2*)&corr[f][j][0];
            __half2 c23 = *(__half2*)&corr[f][j][1];
            float vv[4];
            vv[0] = acc[f][j][0] + __half2float(c01.x);
            vv[1] = acc[f][j][1] + __half2float(c01.y);
            vv[2] = acc[f][j][2] + __half2float(c23.x);
            vv[3] = acc[f][j][3] + __half2float(c23.y);

            int c = wn*64 + j*8 + (lane & 3)*2;
            float b0v = bias[c], b1v = bias[c + 1];
            #pragma unroll
            for (int h = 0; h < 2; h++) {
                int row  = m0 + wm*32 + f*16 + (lane >> 2) + h*8;
                int spos = row & (SEQ - 1);
                float a = vv[2*h]     + b0v;
                float b = vv[2*h + 1] + b1v;
                if (rope) {
                    float cs = g_cos[spos*64 + (c >> 1)];
                    float sn = g_sin[spos*64 + (c >> 1)];
                    float ra = a*cs - b*sn;
                    float rb = b*cs + a*sn;
                    a = ra; b = rb;
                }
                if (mat == 0) {
                    *(uint32_t*)&g_Q16[(size_t)row*HD + c] = pack16(a, b);
                } else if (mat == 1) {
                    uint32_t hi, lo;
                    split_pack(a, b, hi, lo);
                    *(uint32_t*)&g_Khi[(size_t)row*HD + c] = hi;
                    *(uint32_t*)&g_Klo[(size_t)row*HD + c] = lo;
                } else {
                    uint32_t hi, lo;
                    split_pack(a, b, hi, lo);
                    size_t vb = ((size_t)(row >> 12) * HD) * SEQ + (row & (SEQ-1));
                    __half2 H = *(__half2*)&hi;
                    __half2 L = *(__half2*)&lo;
                    g_Vthi[vb + (size_t)c*SEQ]     = H.x;
                    g_Vthi[vb + (size_t)(c+1)*SEQ] = H.y;
                    g_Vtlo[vb + (size_t)c*SEQ]     = L.x;
                    g_Vtlo[vb + (size_t)(c+1)*SEQ] = L.y;
                }
            }
        }
    }
}

// ---------------------------------------------------------------------------
// Flash attention: BM=64, BN=64, 4 warps, 2-term fp16:
//   S  = Q16·(Khi + Klo), PV = P16·(Vhi + Vlo), all fp32 acc.
// smem: Q 16KB + K 32KB + Vt 32KB = 80KB, 2 CTAs/SM.
// ---------------------------------------------------------------------------
#define ATTN_SMEM (80*1024 + 1024)

__global__ __launch_bounds__(128, 2) void attn_mma_kernel(float* __restrict__ out)
{
    extern __shared__ char sm_raw[];
    const uint32_t base = (smem_u32(sm_raw) + 1023) & ~1023u;
    const uint32_t Q16A = base;
    const uint32_t KHI  = base + 16384, KLO  = base + 32768;
    const uint32_t VTHI = base + 49152, VTLO = base + 65536;

    const int tid  = threadIdx.x;
    const int wid  = tid >> 5;
    const int lane = tid & 31;
    const int lr     = lane & 7;
    const int sel    = lane >> 3;
    const int rowadd = (sel & 1) * 8;
    const int kselb  = (sel >> 1) * 16;

    int bxx = blockIdx.x, t;
    if (bxx < 108)      t = 40 + bxx;
    else if (bxx < 148) t = bxx - 108;
    else                t = 403 - bxx;
    const int qt = 63 - (t >> 2);
    const int b  = t & 3;
    const int m0 = qt * 64;

    const __half* q16 = g_Q16 + ((size_t)b*SEQ + m0) * HD;
    const __half* khi = g_Khi + (size_t)b*SEQ*HD;
    const __half* klo = g_Klo + (size_t)b*SEQ*HD;
    const __half* vthi = g_Vthi + (size_t)b*HD*SEQ;
    const __half* vtlo = g_Vtlo + (size_t)b*HD*SEQ;

    // Q tile: 64 rows x 128 d fp16, two 64-d blocks of 128B rows
    #pragma unroll
    for (int it = 0; it < 8; it++) {
        int i = tid + it * 128;
        int row = i >> 4, c = i & 15;
        uint32_t off = (uint32_t)((c >> 3) * 8192)
                     + SW128((uint32_t)(row * 128 + (c & 7) * 16));
        cpasync16(Q16A + off, q16 + (size_t)row * HD + c * 8);
    }
    CP_COMMIT();

    float o[16][4];
    #pragma unroll
    for (int nf = 0; nf < 16; nf++)
        #pragma unroll
        for (int c = 0; c < 4; c++) o[nf][c] = 0.f;
    float mrow0 = -INFINITY, mrow1 = -INFINITY;
    float lsum0 = 0.f, lsum1 = 0.f;
    const float scale = 0.08838834764831845f;

    for (int nt = 0; nt <= qt; nt++) {
        const int nb = nt * 64;
        if (nt) __syncthreads();

        #pragma unroll
        for (int it = 0; it < 8; it++) {
            int i = tid + it * 128;
            int row = i >> 4, c = i & 15;
            uint32_t off = (uint32_t)((c >> 3) * 8192)
                         + SW128((uint32_t)(row * 128 + (c & 7) * 16));
            const size_t g = (size_t)(nb + row) * HD + c * 8;
            cpasync16(KHI + off, khi + g);
            cpasync16(KLO + off, klo + g);
        }
        #pragma unroll
        for (int it = 0; it < 8; it++) {
            int i = tid + it * 128;
            int d = i >> 3, c = i & 7;
            uint32_t off = SW128((uint32_t)(d * 128 + c * 16));
            const size_t g = (size_t)d * SEQ + nb + c * 8;
            cpasync16(VTHI + off, vthi + g);
            cpasync16(VTLO + off, vtlo + g);
        }
        CP_COMMIT();
        CP_WAIT0();
        __syncthreads();

        // ---- S = Q16 (Khi + Klo)  (2 terms, interleaved over 4 accs) ----
        float s[8][4];
        #pragma unroll
        for (int j = 0; j < 8; j++)
            #pragma unroll
            for (int c = 0; c < 4; c++) s[j][c] = 0.f;

        #pragma unroll
        for (int kd = 0; kd < 8; kd++) {
            const uint32_t blk = (uint32_t)((kd >> 2) * 8192);
            const uint32_t kb  = (uint32_t)((kd & 3) * 32 + kselb);
            uint32_t a[4];
            {
                int row = wid*16 + rowadd + lr;
                uint32_t addr = blk + (uint32_t)row*128 + (kb ^ (uint32_t)((row & 7)*16));
                ldsm4(a, Q16A + addr);
            }
            #pragma unroll
            for (int jp = 0; jp < 2; jp++) {
                int rowA = (2*jp)*16 + rowadd + lr;
                int rowB = (2*jp+1)*16 + rowadd + lr;
                uint32_t adA = blk + (uint32_t)rowA*128 + (kb ^ (uint32_t)((rowA & 7)*16));
                uint32_t adB = blk + (uint32_t)rowB*128 + (kb ^ (uint32_t)((rowB & 7)*16));
                uint32_t thA[4], tlA[4], thB[4], tlB[4];
                ldsm4(thA, KHI + adA);
                ldsm4(tlA, KLO + adA);
                ldsm4(thB, KHI + adB);
                ldsm4(tlB, KLO + adB);
                mma16816(s[4*jp],   a, thA[0], thA[2]);
                mma16816(s[4*jp+1], a, thA[1], thA[3]);
                mma16816(s[4*jp+2], a, thB[0], thB[2]);
                mma16816(s[4*jp+3], a, thB[1], thB[3]);
                mma16816(s[4*jp],   a, tlA[0], tlA[2]);
                mma16816(s[4*jp+1], a, tlA[1], tlA[3]);
                mma16816(s[4*jp+2], a, tlB[0], tlB[2]);
                mma16816(s[4*jp+3], a, tlB[1], tlB[3]);
            }
        }

        const bool diag = (nt == qt);
        #pragma unroll
        for (int j = 0; j < 8; j++)
            #pragma unroll
            for (int c = 0; c < 4; c++) {
                float v = s[j][c] * scale;
                if (diag) {
                    int col = j*8 + (lane & 3)*2 + (c & 1);
                    int row = wid*16 + (lane >> 2) + (c >> 1)*8;
                    if (col > row) v = -1e30f;
                }
                s[j][c] = v;
            }

        float mx0 = -INFINITY, mx1 = -INFINITY;
        #pragma unroll
        for (int j = 0; j < 8; j++) {
            mx0 = fmaxf(mx0, fmaxf(s[j][0], s[j][1]));
            mx1 = fmaxf(mx1, fmaxf(s[j][2], s[j][3]));
        }
        mx0 = fmaxf(mx0, __shfl_xor_sync(0xffffffffu, mx0, 1));
        mx0 = fmaxf(mx0, __shfl_xor_sync(0xffffffffu, mx0, 2));
        mx1 = fmaxf(mx1, __shfl_xor_sync(0xffffffffu, mx1, 1));
        mx1 = fmaxf(mx1, __shfl_xor_sync(0xffffffffu, mx1, 2));
        float mn0 = fmaxf(mrow0, mx0), mn1 = fmaxf(mrow1, mx1);
        float al0 = __expf(mrow0 - mn0), al1 = __expf(mrow1 - mn1);
        mrow0 = mn0; mrow1 = mn1;
        float sum0 = 0.f, sum1 = 0.f;
        #pragma unroll
        for (int j = 0; j < 8; j++) {
            s[j][0] = __expf(s[j][0] - mn0); sum0 += s[j][0];
            s[j][1] = __expf(s[j][1] - mn0); sum0 += s[j][1];
            s[j][2] = __expf(s[j][2] - mn1); sum1 += s[j][2];
            s[j][3] = __expf(s[j][3] - mn1); sum1 += s[j][3];
        }
        sum0 += __shfl_xor_sync(0xffffffffu, sum0, 1);
        sum0 += __shfl_xor_sync(0xffffffffu, sum0, 2);
        sum1 += __shfl_xor_sync(0xffffffffu, sum1, 1);
        sum1 += __shfl_xor_sync(0xffffffffu, sum1, 2);
        lsum0 = lsum0 * al0 + sum0;
        lsum1 = lsum1 * al1 + sum1;

        #pragma unroll
        for (int nf = 0; nf < 16; nf++) {
            o[nf][0] *= al0; o[nf][1] *= al0;
            o[nf][2] *= al1; o[nf][3] *= al1;
        }

        // ---- P -> fp16 A-frags (single term) ----
        uint32_t phi[4][4];
        #pragma unroll
        for (int kk = 0; kk < 4; kk++) {
            phi[kk][0] = pack16(s[2*kk][0],   s[2*kk][1]);
            phi[kk][1] = pack16(s[2*kk][2],   s[2*kk][3]);
            phi[kk][2] = pack16(s[2*kk+1][0], s[2*kk+1][1]);
            phi[kk][3] = pack16(s[2*kk+1][2], s[2*kk+1][3]);
        }

        // ---- O += P16 (Vhi + Vlo)  (2 terms, interleaved over jj pairs) ----
        #pragma unroll
        for (int kk = 0; kk < 4; kk++) {
            const uint32_t kb = (uint32_t)(kk*32 + kselb);
            #pragma unroll
            for (int jp = 0; jp < 4; jp++) {
                int rowA = (2*jp)*16 + rowadd + lr;
                int rowB = (2*jp+1)*16 + rowadd + lr;
                uint32_t adA = (uint32_t)rowA*128 + (kb ^ (uint32_t)((rowA & 7)*16));
                uint32_t adB = (uint32_t)rowB*128 + (kb ^ (uint32_t)((rowB & 7)*16));
                uint32_t thA[4], tlA[4], thB[4], tlB[4];
                ldsm4(thA, VTHI + adA);
                ldsm4(tlA, VTLO + adA);
                ldsm4(thB, VTHI + adB);
                ldsm4(tlB, VTLO + adB);
                mma16816(o[4*jp],   phi[kk], thA[0], thA[2]);
                mma16816(o[4*jp+1], phi[kk], thA[1], thA[3]);
                mma16816(o[4*jp+2], phi[kk], thB[0], thB[2]);
                mma16816(o[4*jp+3], phi[kk], thB[1], thB[3]);
                mma16816(o[4*jp],   phi[kk], tlA[0], tlA[2]);
                mma16816(o[4*jp+1], phi[kk], tlA[1], tlA[3]);
                mma16816(o[4*jp+2], phi[kk], tlB[0], tlB[2]);
                mma16816(o[4*jp+3], phi[kk], tlB[1], tlB[3]);
            }
        }
    }

    const float inv0 = 1.0f / lsum0;
    const float inv1 = 1.0f / lsum1;
    const size_t r0 = ((size_t)b*SEQ + m0 + wid*16 + (lane >> 2)) * HD;
    #pragma unroll
    for (int nf = 0; nf < 16; nf++) {
        int c = nf*8 + (lane & 3)*2;
        *(float2*)&out[r0 + c]          = make_float2(o[nf][0]*inv0, o[nf][1]*inv0);
        *(float2*)&out[r0 + 8*HD + c]   = make_float2(o[nf][2]*inv1, o[nf][3]*inv1);
    }
}

// ---------------------------------------------------------------------------
extern "C" void kernel_launch(void* const* d_in, const int* in_sizes, int n_in,
                              void* d_out, int out_size)
{
    const float* x  = (const float*)d_in[0];
    const float* Wq = (const float*)d_in[1];
    const float* bq = (const float*)d_in[2];
    const float* Wk = (const float*)d_in[3];
    const float* bk = (const float*)d_in[4];
    const float* Wv = (const float*)d_in[5];
    const float* bv = (const float*)d_in[6];
    float* out = (float*)d_out;

    rope_table_kernel<<<(SEQ*(HD/2) + 255)/256, 256>>>();
    convert_x_kernel<<<(MTOT*(EMB/4) + 255)/256, 256>>>(x);
    split_w_kernel<<<(3*EMB*HD + 255)/256, 256>>>(Wq, Wk, Wv);

    cudaFuncSetAttribute(qkv_mma_kernel,
                         cudaFuncAttributeMaxDynamicSharedMemorySize, QKV_SMEM);
    dim3 g1(3, MTOT / 128);
    qkv_mma_kernel<<<g1, NTHR, QKV_SMEM>>>(bq, bk, bv);

    cudaFuncSetAttribute(attn_mma_kernel,
                         cudaFuncAttributeMaxDynamicSharedMemorySize, ATTN_SMEM);
    attn_mma_kernel<<<256, 128, ATTN_SMEM>>>(out);
}

// round 17
// speedup vs baseline: 1.8061x; 1.2196x over previous
#include <cuda_runtime.h>
#include <cuda_fp16.h>
#include <math.h>
#include <stdint.h>

#define BATCH 4
#define SEQ   4096
#define EMB   2048
#define HD    128
#define MTOT  (BATCH*SEQ)

// ---------------------------------------------------------------------------
// Device-global scratch (no allocation allowed)
// ---------------------------------------------------------------------------
static __device__ float g_cos[SEQ*(HD/2)];
static __device__ float g_sin[SEQ*(HD/2)];
static __device__ __half g_x16[(size_t)MTOT*EMB];   // fp16(x)
static __device__ __half g_wt16[3*HD*EMB];          // fp16(W^T) [mat][n][k]
static __device__ __half g_Q16[(size_t)MTOT*HD];    // fp16(Q)
static __device__ __half g_Khi[(size_t)MTOT*HD];
static __device__ __half g_Klo[(size_t)MTOT*HD];
static __device__ __half g_Vthi[(size_t)MTOT*HD];   // [b][d][s]
static __device__ __half g_Vtlo[(size_t)MTOT*HD];

// ---------------------------------------------------------------------------
// PTX helpers
// ---------------------------------------------------------------------------
__device__ __forceinline__ uint32_t smem_u32(const void* p) {
    uint32_t a;
    asm("{ .reg .u64 t; cvta.to.shared.u64 t, %1; cvt.u32.u64 %0, t; }" : "=r"(a) : "l"(p));
    return a;
}

#define SW128(off) ((off) ^ (((off) >> 3) & 0x70))

__device__ __forceinline__ void cpasync16(uint32_t dst, const void* src) {
    asm volatile("cp.async.cg.shared.global [%0], [%1], 16;" :: "r"(dst), "l"(src) : "memory");
}
#define CP_COMMIT()  asm volatile("cp.async.commit_group;" ::: "memory")
#define CP_WAIT2()   asm volatile("cp.async.wait_group 2;" ::: "memory")
#define CP_WAIT1()   asm volatile("cp.async.wait_group 1;" ::: "memory")
#define CP_WAIT0()   asm volatile("cp.async.wait_group 0;" ::: "memory")

#define BAR_SYNC(id, cnt)   asm volatile("bar.sync %0, %1;"   :: "r"(id), "r"(cnt) : "memory")
#define BAR_ARRIVE(id, cnt) asm volatile("bar.arrive %0, %1;" :: "r"(id), "r"(cnt) : "memory")
#define MEMBAR_CTA()        asm volatile("membar.cta;" ::: "memory")

__device__ __forceinline__ void ldsm4(uint32_t r[4], uint32_t addr) {
    asm volatile("ldmatrix.sync.aligned.m8n8.x4.shared.b16 {%0,%1,%2,%3}, [%4];"
                 : "=r"(r[0]), "=r"(r[1]), "=r"(r[2]), "=r"(r[3]) : "r"(addr));
}

// f16 inputs, fp32 accumulator
__device__ __forceinline__ void mma16816(float c[4],
                                         const uint32_t a[4],
                                         uint32_t b0, uint32_t b1) {
    asm volatile(
        "mma.sync.aligned.m16n8k16.row.col.f32.f16.f16.f32 "
        "{%0,%1,%2,%3}, {%4,%5,%6,%7}, {%8,%9}, {%0,%1,%2,%3};"
        : "+f"(c[0]), "+f"(c[1]), "+f"(c[2]), "+f"(c[3])
        : "r"(a[0]), "r"(a[1]), "r"(a[2]), "r"(a[3]), "r"(b0), "r"(b1));
}

__device__ __forceinline__ void split_pack(float va, float vb,
                                           uint32_t& hi, uint32_t& lo) {
    __half ha = __float2half(va), hb = __float2half(vb);
    __half2 H(ha, hb);
    hi = *(uint32_t*)&H;
    __half2 L(__float2half(va - __half2float(ha)),
              __float2half(vb - __half2float(hb)));
    lo = *(uint32_t*)&L;
}

__device__ __forceinline__ uint32_t pack16(float va, float vb) {
    __half2 H(__float2half(va), __float2half(vb));
    return *(uint32_t*)&H;
}

// ---------------------------------------------------------------------------
// RoPE tables
// ---------------------------------------------------------------------------
__global__ void rope_table_kernel() {
    int idx = blockIdx.x * blockDim.x + threadIdx.x;
    if (idx >= SEQ * (HD/2)) return;
    int s = idx >> 6;
    int i = idx & 63;
    double freqd = exp(-(double)(2*i) * (9.210340371976184 / 128.0));
    float angle = (float)s * (float)freqd;
    float sn, cs;
    sincosf(angle, &sn, &cs);
    g_cos[idx] = cs;
    g_sin[idx] = sn;
}

// ---------------------------------------------------------------------------
// x -> fp16, W -> fp16 transposed
// ---------------------------------------------------------------------------
__global__ void convert_x_kernel(const float* __restrict__ x) {
    size_t idx = (size_t)blockIdx.x * blockDim.x + threadIdx.x;   // per float4
    if (idx >= (size_t)MTOT * EMB / 4) return;
    float4 v = ((const float4*)x)[idx];
    ((uint32_t*)g_x16)[2*idx]   = pack16(v.x, v.y);
    ((uint32_t*)g_x16)[2*idx+1] = pack16(v.z, v.w);
}

__global__ void convert_w_kernel(const float* __restrict__ Wq,
                                 const float* __restrict__ Wk,
                                 const float* __restrict__ Wv) {
    int idx = blockIdx.x * blockDim.x + threadIdx.x;   // 3*EMB*HD
    if (idx >= 3 * EMB * HD) return;
    int mat = idx / (EMB * HD);
    int r   = idx % (EMB * HD);
    int k = r / HD, n = r % HD;
    const float* W = (mat == 0) ? Wq : (mat == 1) ? Wk : Wv;
    g_wt16[(size_t)mat*HD*EMB + (size_t)n*EMB + k] = __float2half(W[r]);
}

// ---------------------------------------------------------------------------
// QKV projection: single-term fp16 GEMM (x16·w16), fp32 acc.
// Warp-specialized producer/consumer; stage = A + B = 32KB.
// ---------------------------------------------------------------------------
#define KC       64
#define NCHUNK   (EMB / KC)          // 32
#define TILE_B   16384               // 128 rows x 128 bytes
#define STAGE_B  (2 * TILE_B)        // A, B
#define QKV_SMEM (1024 + 3 * STAGE_B)
#define NTHR     384

__global__ __launch_bounds__(NTHR, 1) void qkv_mma_kernel(
    const float* __restrict__ Bq, const float* __restrict__ Bk,
    const float* __restrict__ Bv)
{
    extern __shared__ char smem_raw[];
    uint32_t base = (smem_u32(smem_raw) + 1023) & ~1023u;
    const int tid  = threadIdx.x;
    const int wid  = tid >> 5;
    const int lane = tid & 31;
    const int mat  = blockIdx.x;
    const int m0   = blockIdx.y * 128;

    const __half* A16 = g_x16 + (size_t)m0 * EMB;
    const __half* B16 = g_wt16 + (size_t)mat * HD * EMB;
    const float* bias = (mat == 0) ? Bq : (mat == 1) ? Bk : Bv;

    if (wid >= 8) {
        const int ptid = tid - 256;    // 0..127
        for (int i = 0; i < NCHUNK; i++) {
            const int s = i - (i / 3) * 3;
            if (i >= 3) BAR_SYNC(4 + s, NTHR);
            const int k0 = i * KC;
            const uint32_t st = base + s * STAGE_B;
            #pragma unroll
            for (int t = 0; t < 8; t++) {
                int idx = ptid + t * 128;
                int row = idx >> 3;
                int c16 = idx & 7;
                uint32_t off = SW128((uint32_t)(row * 128 + c16 * 16));
                const size_t g = (size_t)row * EMB + k0 + c16 * 8;
                cpasync16(st + 0*TILE_B + off, A16 + g);
                cpasync16(st + 1*TILE_B + off, B16 + g);
            }
            CP_COMMIT();
            if (i >= 2) {
                CP_WAIT2();
                MEMBAR_CTA();
                BAR_ARRIVE(1 + ((i - 2) % 3), NTHR);
            }
        }
        CP_WAIT1(); MEMBAR_CTA(); BAR_ARRIVE(1 + ((NCHUNK - 2) % 3), NTHR);
        CP_WAIT0(); MEMBAR_CTA(); BAR_ARRIVE(1 + ((NCHUNK - 1) % 3), NTHR);
        return;
    }

    const int wm = wid & 3;
    const int wn = wid >> 2;
    const int lr     = lane & 7;
    const int sel    = lane >> 3;
    const int rowadd = (sel & 1) * 8;
    const int kselb  = (sel >> 1) * 16;

    float acc[2][8][4];
    #pragma unroll
    for (int i = 0; i < 2; i++)
        #pragma unroll
        for (int j = 0; j < 8; j++)
            #pragma unroll
            for (int c = 0; c < 4; c++) acc[i][j][c] = 0.f;

    for (int i = 0; i < NCHUNK; i++) {
        const int s = i - (i / 3) * 3;
        BAR_SYNC(1 + s, NTHR);

        const uint32_t st = base + s * STAGE_B;
        const uint32_t aB = st;
        const uint32_t bB = st + TILE_B;

        #pragma unroll
        for (int kk = 0; kk < 4; kk++) {
            const int kb = kk * 32;

            uint32_t af[2][4];
            #pragma unroll
            for (int f = 0; f < 2; f++) {
                int row = wm*32 + f*16 + rowadd + lr;
                uint32_t byte = (uint32_t)(kb + kselb) ^ (uint32_t)((row & 7) * 16);
                uint32_t off  = (uint32_t)row * 128 + byte;
                ldsm4(af[f], aB + off);
            }
            uint32_t bf[8][2];
            #pragma unroll
            for (int jj = 0; jj < 4; jj++) {
                int row = wn*64 + jj*16 + rowadd + lr;
                uint32_t byte = (uint32_t)(kb + kselb) ^ (uint32_t)((row & 7) * 16);
                uint32_t off  = (uint32_t)row * 128 + byte;
                uint32_t t[4];
                ldsm4(t, bB + off);
                bf[2*jj][0]   = t[0]; bf[2*jj][1]   = t[2];
                bf[2*jj+1][0] = t[1]; bf[2*jj+1][1] = t[3];
            }
            #pragma unroll
            for (int f = 0; f < 2; f++)
                #pragma unroll
                for (int j = 0; j < 8; j++)
                    mma16816(acc[f][j], af[f], bf[j][0], bf[j][1]);
        }

        BAR_ARRIVE(4 + s, NTHR);
    }

    // Epilogue: bias (+RoPE for Q,K); Q unsplit, K split, Vt split.
    const bool rope = (mat < 2);
    #pragma unroll
    for (int f = 0; f < 2; f++) {
        #pragma unroll
        for (int j = 0; j < 8; j++) {
            int c = wn*64 + j*8 + (lane & 3)*2;
            float b0v = bias[c], b1v = bias[c + 1];
            #pragma unroll
            for (int h = 0; h < 2; h++) {
                int row  = m0 + wm*32 + f*16 + (lane >> 2) + h*8;
                int spos = row & (SEQ - 1);
                float a = acc[f][j][2*h]     + b0v;
                float b = acc[f][j][2*h + 1] + b1v;
                if (rope) {
                    float cs = g_cos[spos*64 + (c >> 1)];
                    float sn = g_sin[spos*64 + (c >> 1)];
                    float ra = a*cs - b*sn;
                    float rb = b*cs + a*sn;
                    a = ra; b = rb;
                }
                if (mat == 0) {
                    *(uint32_t*)&g_Q16[(size_t)row*HD + c] = pack16(a, b);
                } else if (mat == 1) {
                    uint32_t hi, lo;
                    split_pack(a, b, hi, lo);
                    *(uint32_t*)&g_Khi[(size_t)row*HD + c] = hi;
                    *(uint32_t*)&g_Klo[(size_t)row*HD + c] = lo;
                } else {
                    uint32_t hi, lo;
                    split_pack(a, b, hi, lo);
                    size_t vb = ((size_t)(row >> 12) * HD) * SEQ + (row & (SEQ-1));
                    __half2 H = *(__half2*)&hi;
                    __half2 L = *(__half2*)&lo;
                    g_Vthi[vb + (size_t)c*SEQ]     = H.x;
                    g_Vthi[vb + (size_t)(c+1)*SEQ] = H.y;
                    g_Vtlo[vb + (size_t)c*SEQ]     = L.x;
                    g_Vtlo[vb + (size_t)(c+1)*SEQ] = L.y;
                }
            }
        }
    }
}

// ---------------------------------------------------------------------------
// Flash attention: BM=64, BN=64, 4 warps, 2-term fp16 (unchanged from R15):
//   S  = Q16·(Khi + Klo), PV = P16·(Vhi + Vlo), all fp32 acc.
// smem: Q 16KB + K 32KB + Vt 32KB = 80KB, 2 CTAs/SM.
// ---------------------------------------------------------------------------
#define ATTN_SMEM (80*1024 + 1024)

__global__ __launch_bounds__(128, 2) void attn_mma_kernel(float* __restrict__ out)
{
    extern __shared__ char sm_raw[];
    const uint32_t base = (smem_u32(sm_raw) + 1023) & ~1023u;
    const uint32_t Q16A = base;
    const uint32_t KHI  = base + 16384, KLO  = base + 32768;
    const uint32_t VTHI = base + 49152, VTLO = base + 65536;

    const int tid  = threadIdx.x;
    const int wid  = tid >> 5;
    const int lane = tid & 31;
    const int lr     = lane & 7;
    const int sel    = lane >> 3;
    const int rowadd = (sel & 1) * 8;
    const int kselb  = (sel >> 1) * 16;

    int bxx = blockIdx.x, t;
    if (bxx < 108)      t = 40 + bxx;
    else if (bxx < 148) t = bxx - 108;
    else                t = 403 - bxx;
    const int qt = 63 - (t >> 2);
    const int b  = t & 3;
    const int m0 = qt * 64;

    const __half* q16 = g_Q16 + ((size_t)b*SEQ + m0) * HD;
    const __half* khi = g_Khi + (size_t)b*SEQ*HD;
    const __half* klo = g_Klo + (size_t)b*SEQ*HD;
    const __half* vthi = g_Vthi + (size_t)b*HD*SEQ;
    const __half* vtlo = g_Vtlo + (size_t)b*HD*SEQ;

    #pragma unroll
    for (int it = 0; it < 8; it++) {
        int i = tid + it * 128;
        int row = i >> 4, c = i & 15;
        uint32_t off = (uint32_t)((c >> 3) * 8192)
                     + SW128((uint32_t)(row * 128 + (c & 7) * 16));
        cpasync16(Q16A + off, q16 + (size_t)row * HD + c * 8);
    }
    CP_COMMIT();

    float o[16][4];
    #pragma unroll
    for (int nf = 0; nf < 16; nf++)
        #pragma unroll
        for (int c = 0; c < 4; c++) o[nf][c] = 0.f;
    float mrow0 = -INFINITY, mrow1 = -INFINITY;
    float lsum0 = 0.f, lsum1 = 0.f;
    const float scale = 0.08838834764831845f;

    for (int nt = 0; nt <= qt; nt++) {
        const int nb = nt * 64;
        if (nt) __syncthreads();

        #pragma unroll
        for (int it = 0; it < 8; it++) {
            int i = tid + it * 128;
            int row = i >> 4, c = i & 15;
            uint32_t off = (uint32_t)((c >> 3) * 8192)
                         + SW128((uint32_t)(row * 128 + (c & 7) * 16));
            const size_t g = (size_t)(nb + row) * HD + c * 8;
            cpasync16(KHI + off, khi + g);
            cpasync16(KLO + off, klo + g);
        }
        #pragma unroll
        for (int it = 0; it < 8; it++) {
            int i = tid + it * 128;
            int d = i >> 3, c = i & 7;
            uint32_t off = SW128((uint32_t)(d * 128 + c * 16));
            const size_t g = (size_t)d * SEQ + nb + c * 8;
            cpasync16(VTHI + off, vthi + g);
            cpasync16(VTLO + off, vtlo + g);
        }
        CP_COMMIT();
        CP_WAIT0();
        __syncthreads();

        float s[8][4];
        #pragma unroll
        for (int j = 0; j < 8; j++)
            #pragma unroll
            for (int c = 0; c < 4; c++) s[j][c] = 0.f;

        #pragma unroll
        for (int kd = 0; kd < 8; kd++) {
            const uint32_t blk = (uint32_t)((kd >> 2) * 8192);
            const uint32_t kb  = (uint32_t)((kd & 3) * 32 + kselb);
            uint32_t a[4];
            {
                int row = wid*16 + rowadd + lr;
                uint32_t addr = blk + (uint32_t)row*128 + (kb ^ (uint32_t)((row & 7)*16));
                ldsm4(a, Q16A + addr);
            }
            #pragma unroll
            for (int jp = 0; jp < 2; jp++) {
                int rowA = (2*jp)*16 + rowadd + lr;
                int rowB = (2*jp+1)*16 + rowadd + lr;
                uint32_t adA = blk + (uint32_t)rowA*128 + (kb ^ (uint32_t)((rowA & 7)*16));
                uint32_t adB = blk + (uint32_t)rowB*128 + (kb ^ (uint32_t)((rowB & 7)*16));
                uint32_t thA[4], tlA[4], thB[4], tlB[4];
                ldsm4(thA, KHI + adA);
                ldsm4(tlA, KLO + adA);
                ldsm4(thB, KHI + adB);
                ldsm4(tlB, KLO + adB);
                mma16816(s[4*jp],   a, thA[0], thA[2]);
                mma16816(s[4*jp+1], a, thA[1], thA[3]);
                mma16816(s[4*jp+2], a, thB[0], thB[2]);
                mma16816(s[4*jp+3], a, thB[1], thB[3]);
                mma16816(s[4*jp],   a, tlA[0], tlA[2]);
                mma16816(s[4*jp+1], a, tlA[1], tlA[3]);
                mma16816(s[4*jp+2], a, tlB[0], tlB[2]);
                mma16816(s[4*jp+3], a, tlB[1], tlB[3]);
            }
        }

        const bool diag = (nt == qt);
        #pragma unroll
        for (int j = 0; j < 8; j++)
            #pragma unroll
            for (int c = 0; c < 4; c++) {
                float v = s[j][c] * scale;
                if (diag) {
                    int col = j*8 + (lane & 3)*2 + (c & 1);
                    int row = wid*16 + (lane >> 2) + (c >> 1)*8;
                    if (col > row) v = -1e30f;
                }
                s[j][c] = v;
            }

        float mx0 = -INFINITY, mx1 = -INFINITY;
        #pragma unroll
        for (int j = 0; j < 8; j++) {
            mx0 = fmaxf(mx0, fmaxf(s[j][0], s[j][1]));
            mx1 = fmaxf(mx1, fmaxf(s[j][2], s[j][3]));
        }
        mx0 = fmaxf(mx0, __shfl_xor_sync(0xffffffffu, mx0, 1));
        mx0 = fmaxf(mx0, __shfl_xor_sync(0xffffffffu, mx0, 2));
        mx1 = fmaxf(mx1, __shfl_xor_sync(0xffffffffu, mx1, 1));
        mx1 = fmaxf(mx1, __shfl_xor_sync(0xffffffffu, mx1, 2));
        float mn0 = fmaxf(mrow0, mx0), mn1 = fmaxf(mrow1, mx1);
        float al0 = __expf(mrow0 - mn0), al1 = __expf(mrow1 - mn1);
        mrow0 = mn0; mrow1 = mn1;
        float sum0 = 0.f, sum1 = 0.f;
        #pragma unroll
        for (int j = 0; j < 8; j++) {
            s[j][0] = __expf(s[j][0] - mn0); sum0 += s[j][0];
            s[j][1] = __expf(s[j][1] - mn0); sum0 += s[j][1];
            s[j][2] = __expf(s[j][2] - mn1); sum1 += s[j][2];
            s[j][3] = __expf(s[j][3] - mn1); sum1 += s[j][3];
        }
        sum0 += __shfl_xor_sync(0xffffffffu, sum0, 1);
        sum0 += __shfl_xor_sync(0xffffffffu, sum0, 2);
        sum1 += __shfl_xor_sync(0xffffffffu, sum1, 1);
        sum1 += __shfl_xor_sync(0xffffffffu, sum1, 2);
        lsum0 = lsum0 * al0 + sum0;
        lsum1 = lsum1 * al1 + sum1;

        #pragma unroll
        for (int nf = 0; nf < 16; nf++) {
            o[nf][0] *= al0; o[nf][1] *= al0;
            o[nf][2] *= al1; o[nf][3] *= al1;
        }

        uint32_t phi[4][4];
        #pragma unroll
        for (int kk = 0; kk < 4; kk++) {
            phi[kk][0] = pack16(s[2*kk][0],   s[2*kk][1]);
            phi[kk][1] = pack16(s[2*kk][2],   s[2*kk][3]);
            phi[kk][2] = pack16(s[2*kk+1][0], s[2*kk+1][1]);
            phi[kk][3] = pack16(s[2*kk+1][2], s[2*kk+1][3]);
        }

        #pragma unroll
        for (int kk = 0; kk < 4; kk++) {
            const uint32_t kb = (uint32_t)(kk*32 + kselb);
            #pragma unroll
            for (int jp = 0; jp < 4; jp++) {
                int rowA = (2*jp)*16 + rowadd + lr;
                int rowB = (2*jp+1)*16 + rowadd + lr;
                uint32_t adA = (uint32_t)rowA*128 + (kb ^ (uint32_t)((rowA & 7)*16));
                uint32_t adB = (uint32_t)rowB*128 + (kb ^ (uint32_t)((rowB & 7)*16));
                uint32_t thA[4], tlA[4], thB[4], tlB[4];
                ldsm4(thA, VTHI + adA);
                ldsm4(tlA, VTLO + adA);
                ldsm4(thB, VTHI + adB);
                ldsm4(tlB, VTLO + adB);
                mma16816(o[4*jp],   phi[kk], thA[0], thA[2]);
                mma16816(o[4*jp+1], phi[kk], thA[1], thA[3]);
                mma16816(o[4*jp+2], phi[kk], thB[0], thB[2]);
                mma16816(o[4*jp+3], phi[kk], thB[1], thB[3]);
                mma16816(o[4*jp],   phi[kk], tlA[0], tlA[2]);
                mma16816(o[4*jp+1], phi[kk], tlA[1], tlA[3]);
                mma16816(o[4*jp+2], phi[kk], tlB[0], tlB[2]);
                mma16816(o[4*jp+3], phi[kk], tlB[1], tlB[3]);
            }
        }
    }

    const float inv0 = 1.0f / lsum0;
    const float inv1 = 1.0f / lsum1;
    const size_t r0 = ((size_t)b*SEQ + m0 + wid*16 + (lane >> 2)) * HD;
    #pragma unroll
    for (int nf = 0; nf < 16; nf++) {
        int c = nf*8 + (lane & 3)*2;
        *(float2*)&out[r0 + c]          = make_float2(o[nf][0]*inv0, o[nf][1]*inv0);
        *(float2*)&out[r0 + 8*HD + c]   = make_float2(o[nf][2]*inv1, o[nf][3]*inv1);
    }
}

// ---------------------------------------------------------------------------
extern "C" void kernel_launch(void* const* d_in, const int* in_sizes, int n_in,
                              void* d_out, int out_size)
{
    const float* x  = (const float*)d_in[0];
    const float* Wq = (const float*)d_in[1];
    const float* bq = (const float*)d_in[2];
    const float* Wk = (const float*)d_in[3];
    const float* bk = (const float*)d_in[4];
    const float* Wv = (const float*)d_in[5];
    const float* bv = (const float*)d_in[6];
    float* out = (float*)d_out;

    rope_table_kernel<<<(SEQ*(HD/2) + 255)/256, 256>>>();
    convert_x_kernel<<<(MTOT*(EMB/4) + 255)/256, 256>>>(x);
    convert_w_kernel<<<(3*EMB*HD + 255)/256, 256>>>(Wq, Wk, Wv);

    cudaFuncSetAttribute(qkv_mma_kernel,
                         cudaFuncAttributeMaxDynamicSharedMemorySize, QKV_SMEM);
    dim3 g1(3, MTOT / 128);
    qkv_mma_kernel<<<g1, NTHR, QKV_SMEM>>>(bq, bk, bv);

    cudaFuncSetAttribute(attn_mma_kernel,
                         cudaFuncAttributeMaxDynamicSharedMemorySize, ATTN_SMEM);
    attn_mma_kernel<<<256, 128, ATTN_SMEM>>>(out);
}